// round 3
// baseline (speedup 1.0000x reference)
#include <cuda_runtime.h>
#include <math.h>

#define Bc   8
#define Tc   2048
#define Ec   64
#define Hc   8
#define DKc  8
#define FFc  256
#define NTOK (Bc*Tc)

typedef unsigned long long u64;

// ---- packed f32x2 helpers (sm_103a FFMA2 path; bit-exact fp32 per lane) ----
__device__ __forceinline__ u64 pack2(float lo, float hi) {
    u64 r; asm("mov.b64 %0,{%1,%2};" : "=l"(r) : "f"(lo), "f"(hi)); return r;
}
__device__ __forceinline__ void unpack2(u64 v, float& a, float& b) {
    asm("mov.b64 {%0,%1},%2;" : "=f"(a), "=f"(b) : "l"(v));
}
__device__ __forceinline__ u64 fma2(u64 a, u64 b, u64 c) {
    u64 d; asm("fma.rn.f32x2 %0,%1,%2,%3;" : "=l"(d) : "l"(a), "l"(b), "l"(c)); return d;
}
__device__ __forceinline__ u64 mul2(u64 a, u64 b) {
    u64 d; asm("mul.rn.f32x2 %0,%1,%2;" : "=l"(d) : "l"(a), "l"(b)); return d;
}
__device__ __forceinline__ u64 add2(u64 a, u64 b) {
    u64 d; asm("add.rn.f32x2 %0,%1,%2;" : "=l"(d) : "l"(a), "l"(b)); return d;
}

// Scratch (device globals: no allocations allowed)
__device__ float g_q[Bc*Hc*Tc*DKc];     // [b,h,t,d]
__device__ float g_k[Bc*Hc*Tc*DKc];
__device__ float g_v[Bc*Hc*Tc*DKc];
__device__ float g_attn[NTOK*Ec];       // [n, e] with e = h*8+d
__device__ float g_x1[NTOK*Ec];
__device__ float g_h[(size_t)FFc*NTOK]; // f-major: [f, n] for coalesced access

// ---------------------------------------------------------------------------
// K1: q/k/v = cos(x @ W^T + b + theta_attn), written [b,h,t,d]
// ---------------------------------------------------------------------------
__global__ __launch_bounds__(128) void qkv_kernel(
    const float* __restrict__ x,
    const float* __restrict__ Wq, const float* __restrict__ bq,
    const float* __restrict__ Wk, const float* __restrict__ bk,
    const float* __restrict__ Wv, const float* __restrict__ bv,
    const float* __restrict__ theta_p)
{
    extern __shared__ float sm[];
    float* sWq = sm;
    float* sWk = sm + 4096;
    float* sWv = sm + 8192;
    float* sb  = sm + 12288;
    int tid = threadIdx.x;
    for (int i = tid; i < 4096; i += 128) { sWq[i] = Wq[i]; sWk[i] = Wk[i]; sWv[i] = Wv[i]; }
    if (tid < 64) { sb[tid] = bq[tid]; sb[64+tid] = bk[tid]; sb[128+tid] = bv[tid]; }
    __syncthreads();

    float theta = theta_p[0];
    int n = blockIdx.x * 128 + tid;

    u64 x2[32];
    const ulonglong2* xp = reinterpret_cast<const ulonglong2*>(x + (size_t)n * Ec);
#pragma unroll
    for (int i = 0; i < 16; i++) { ulonglong2 v = xp[i]; x2[2*i] = v.x; x2[2*i+1] = v.y; }

    int b = n >> 11, t = n & 2047;
    int base = b * (Hc*Tc*DKc) + t * DKc;

    for (int h = 0; h < Hc; h++) {
        float q8[8], k8[8], v8[8];
#pragma unroll
        for (int d = 0; d < 8; d++) {
            int o = h*8 + d;
            const ulonglong2* wq = reinterpret_cast<const ulonglong2*>(sWq + o*64);
            const ulonglong2* wk = reinterpret_cast<const ulonglong2*>(sWk + o*64);
            const ulonglong2* wv = reinterpret_cast<const ulonglong2*>(sWv + o*64);
            u64 qa=0,qb_=0,ka=0,kb_=0,va=0,vb_=0;
#pragma unroll
            for (int i = 0; i < 16; i++) {
                ulonglong2 a = wq[i], c = wk[i], e = wv[i];
                qa  = fma2(x2[2*i], a.x, qa);  qb_ = fma2(x2[2*i+1], a.y, qb_);
                ka  = fma2(x2[2*i], c.x, ka);  kb_ = fma2(x2[2*i+1], c.y, kb_);
                va  = fma2(x2[2*i], e.x, va);  vb_ = fma2(x2[2*i+1], e.y, vb_);
            }
            float l0,h0,l1,h1,l2,h2;
            unpack2(add2(qa,qb_), l0, h0);
            unpack2(add2(ka,kb_), l1, h1);
            unpack2(add2(va,vb_), l2, h2);
            q8[d] = __cosf(l0 + h0 + sb[o]       + theta);
            k8[d] = __cosf(l1 + h1 + sb[64+o]    + theta);
            v8[d] = __cosf(l2 + h2 + sb[128+o]   + theta);
        }
        int off = base + h * (Tc*DKc);
        *reinterpret_cast<float4*>(g_q + off)     = make_float4(q8[0],q8[1],q8[2],q8[3]);
        *reinterpret_cast<float4*>(g_q + off + 4) = make_float4(q8[4],q8[5],q8[6],q8[7]);
        *reinterpret_cast<float4*>(g_k + off)     = make_float4(k8[0],k8[1],k8[2],k8[3]);
        *reinterpret_cast<float4*>(g_k + off + 4) = make_float4(k8[4],k8[5],k8[6],k8[7]);
        *reinterpret_cast<float4*>(g_v + off)     = make_float4(v8[0],v8[1],v8[2],v8[3]);
        *reinterpret_cast<float4*>(g_v + off + 4) = make_float4(v8[4],v8[5],v8[6],v8[7]);
    }
}

// ---------------------------------------------------------------------------
// K2: attention, f32x2 packed inner loop. 1024 CTAs x 128 threads (7 waves).
// Bounded scores (|s|<=2.83): single-pass softmax, log2e folded into q.
// ---------------------------------------------------------------------------
__global__ __launch_bounds__(128) void attn_kernel()
{
    extern __shared__ float sm[];
    ulonglong2* K2s = reinterpret_cast<ulonglong2*>(sm);
    ulonglong2* V2s = reinterpret_cast<ulonglong2*>(sm + Tc*DKc);

    int bh  = blockIdx.x;   // 0..63
    int qt  = blockIdx.y;   // 0..15
    int tid = threadIdx.x;

    const ulonglong2* gk = reinterpret_cast<const ulonglong2*>(g_k + (size_t)bh * (Tc*DKc));
    const ulonglong2* gv = reinterpret_cast<const ulonglong2*>(g_v + (size_t)bh * (Tc*DKc));
    // K and V are each Tc*DKc/4 = 4096 ulonglong2 -> 32 iterations of 128 threads
#pragma unroll
    for (int i = 0; i < 32; i++) {
        K2s[tid + 128*i] = gk[tid + 128*i];
        V2s[tid + 128*i] = gv[tid + 128*i];
    }
    __syncthreads();

    int t = qt * 128 + tid;
    const float* qp = g_q + (size_t)bh * (Tc*DKc) + t * DKc;
    const float QS = 0.35355339059327f * 1.4426950408889634f;  // 1/sqrt(8)*log2(e)
    u64 q01 = pack2(qp[0]*QS, qp[1]*QS);
    u64 q23 = pack2(qp[2]*QS, qp[3]*QS);
    u64 q45 = pack2(qp[4]*QS, qp[5]*QS);
    u64 q67 = pack2(qp[6]*QS, qp[7]*QS);

    float l = 0.f;
    u64 a01 = 0, a23 = 0, a45 = 0, a67 = 0;

    const ulonglong2* kp = K2s;
    const ulonglong2* vp = V2s;
#pragma unroll 4
    for (int j = 0; j < Tc; j++) {
        ulonglong2 ka = kp[0], kb = kp[1]; kp += 2;
        u64 d = mul2(q01, ka.x);
        d = fma2(q23, ka.y, d);
        d = fma2(q45, kb.x, d);
        d = fma2(q67, kb.y, d);
        float slo, shi; unpack2(d, slo, shi);
        float s = slo + shi;
        float p;
        asm("ex2.approx.f32 %0, %1;" : "=f"(p) : "f"(s));
        ulonglong2 va = vp[0], vb = vp[1]; vp += 2;
        u64 pp = pack2(p, p);
        l += p;
        a01 = fma2(pp, va.x, a01);
        a23 = fma2(pp, va.y, a23);
        a45 = fma2(pp, vb.x, a45);
        a67 = fma2(pp, vb.y, a67);
    }
    float inv = 1.0f / l;

    float o0,o1,o2,o3,o4,o5,o6,o7;
    unpack2(a01,o0,o1); unpack2(a23,o2,o3); unpack2(a45,o4,o5); unpack2(a67,o6,o7);
    int b = bh >> 3, h = bh & 7;
    float* op = g_attn + ((size_t)(b*Tc + t)) * Ec + h * DKc;
    reinterpret_cast<float4*>(op)[0] = make_float4(o0*inv, o1*inv, o2*inv, o3*inv);
    reinterpret_cast<float4*>(op)[1] = make_float4(o4*inv, o5*inv, o6*inv, o7*inv);
}

// ---------------------------------------------------------------------------
// K3: x1 = LN(x + attn @ Wo^T + bo).  Residual rows staged in padded smem
// (pitch 65 -> conflict-free) so only the attn row lives in registers.
// ---------------------------------------------------------------------------
__global__ __launch_bounds__(128) void oproj_kernel(
    const float* __restrict__ x, const float* __restrict__ Wo,
    const float* __restrict__ bo, const float* __restrict__ g1,
    const float* __restrict__ be1)
{
    extern __shared__ float sm[];
    float* sWo = sm;              // 4096
    float* sbo = sm + 4096;       // 64
    float* sg  = sm + 4160;       // 64
    float* sbe = sm + 4224;       // 64
    float* sR  = sm + 4288;       // 128 * 65
    int tid = threadIdx.x;
    for (int i = tid; i < 4096; i += 128) sWo[i] = Wo[i];
    if (tid < 64) { sbo[tid] = bo[tid]; sg[tid] = g1[tid]; sbe[tid] = be1[tid]; }
    size_t xbase = (size_t)blockIdx.x * 128 * Ec;
    for (int i = tid; i < 128*Ec; i += 128) {
        int tt = i >> 6, e = i & 63;
        sR[tt*65 + e] = x[xbase + i];
    }
    __syncthreads();

    int n = blockIdx.x * 128 + tid;
    u64 a2[32];
    const ulonglong2* ap = reinterpret_cast<const ulonglong2*>(g_attn + (size_t)n * Ec);
#pragma unroll
    for (int i = 0; i < 16; i++) { ulonglong2 v = ap[i]; a2[2*i] = v.x; a2[2*i+1] = v.y; }

    float* myR = sR + tid*65;
    float s1 = 0.f;
    for (int e = 0; e < 64; e++) {
        const ulonglong2* w = reinterpret_cast<const ulonglong2*>(sWo + e*64);
        u64 c0 = 0, c1 = 0;
#pragma unroll
        for (int i = 0; i < 16; i++) {
            ulonglong2 ww = w[i];
            c0 = fma2(a2[2*i],   ww.x, c0);
            c1 = fma2(a2[2*i+1], ww.y, c1);
        }
        float lo, hi; unpack2(add2(c0, c1), lo, hi);
        float rv = myR[e] + lo + hi + sbo[e];
        myR[e] = rv;
        s1 += rv;
    }
    float m = s1 * (1.f/64.f);
    float s2 = 0.f;
#pragma unroll
    for (int e = 0; e < 64; e++) { float d = myR[e] - m; s2 = fmaf(d, d, s2); }
    float rs = rsqrtf(s2 * (1.f/64.f) + 1e-5f);

    float* o = g_x1 + (size_t)n * Ec;
#pragma unroll
    for (int i = 0; i < 16; i++) {
        float4 v;
        v.x = (myR[4*i+0] - m) * rs * sg[4*i+0] + sbe[4*i+0];
        v.y = (myR[4*i+1] - m) * rs * sg[4*i+1] + sbe[4*i+1];
        v.z = (myR[4*i+2] - m) * rs * sg[4*i+2] + sbe[4*i+2];
        v.w = (myR[4*i+3] - m) * rs * sg[4*i+3] + sbe[4*i+3];
        reinterpret_cast<float4*>(o)[i] = v;
    }
}

// ---------------------------------------------------------------------------
// K4a: H[f,n] = relu(cos(x1)*cos(theta) @ W1^T + b1)   (f-major, coalesced)
// ---------------------------------------------------------------------------
__global__ __launch_bounds__(128) void ffn_h_kernel(
    const float* __restrict__ W1, const float* __restrict__ b1,
    const float* __restrict__ theta_p)
{
    extern __shared__ float sm[];
    float* sW1 = sm;             // 16384
    float* sb1 = sm + 16384;     // 256
    int tid = threadIdx.x;
    for (int i = tid; i < 16384; i += 128) sW1[i] = W1[i];
    for (int i = tid; i < 256; i += 128) sb1[i] = b1[i];
    __syncthreads();

    float ct = __cosf(theta_p[0]);
    int n = blockIdx.x * 128 + tid;

    u64 qc[32];
    const ulonglong2* xp = reinterpret_cast<const ulonglong2*>(g_x1 + (size_t)n * Ec);
#pragma unroll
    for (int i = 0; i < 16; i++) {
        ulonglong2 v = xp[i];
        float a,b,c,d;
        unpack2(v.x, a, b); unpack2(v.y, c, d);
        qc[2*i]   = pack2(__cosf(a)*ct, __cosf(b)*ct);
        qc[2*i+1] = pack2(__cosf(c)*ct, __cosf(d)*ct);
    }

#pragma unroll 2
    for (int f = 0; f < FFc; f++) {
        const ulonglong2* w = reinterpret_cast<const ulonglong2*>(sW1 + f*64);
        u64 h0 = 0, h1 = 0;
#pragma unroll
        for (int i = 0; i < 16; i++) {
            ulonglong2 ww = w[i];
            h0 = fma2(qc[2*i],   ww.x, h0);
            h1 = fma2(qc[2*i+1], ww.y, h1);
        }
        float lo, hi; unpack2(add2(h0, h1), lo, hi);
        float hf = fmaxf(lo + hi + sb1[f], 0.f);
        g_h[(size_t)f * NTOK + n] = hf;
    }
}

// ---------------------------------------------------------------------------
// K4b: out = LN(x1 + H @ W2^T + b2).  W2 transposed into padded smem.
// ---------------------------------------------------------------------------
__global__ __launch_bounds__(128) void ffn_out_kernel(
    const float* __restrict__ W2, const float* __restrict__ b2,
    const float* __restrict__ g2, const float* __restrict__ be2,
    float* __restrict__ out)
{
#define W2P 68   // pitch: 68*4 = 272 B, 16B aligned
    extern __shared__ float sm[];
    float* sW2t = sm;               // 256 * 68
    float* sb2  = sm + 256*W2P;     // 64
    float* sg   = sb2 + 64;
    float* sbe  = sg + 64;
    int tid = threadIdx.x;
    for (int i = tid; i < Ec*FFc; i += 128) {
        int e = i >> 8, f = i & 255;
        sW2t[f*W2P + e] = W2[i];
    }
    if (tid < 64) { sb2[tid] = b2[tid]; sg[tid] = g2[tid]; sbe[tid] = be2[tid]; }
    __syncthreads();

    int n = blockIdx.x * 128 + tid;

    u64 y2[32];
    const ulonglong2* xp = reinterpret_cast<const ulonglong2*>(g_x1 + (size_t)n * Ec);
#pragma unroll
    for (int i = 0; i < 16; i++) {
        ulonglong2 v = xp[i];
        float a,b,c,d;
        unpack2(v.x, a, b); unpack2(v.y, c, d);
        y2[2*i]   = pack2(a + sb2[4*i+0], b + sb2[4*i+1]);
        y2[2*i+1] = pack2(c + sb2[4*i+2], d + sb2[4*i+3]);
    }

#pragma unroll 2
    for (int f = 0; f < FFc; f++) {
        float hf = __ldg(&g_h[(size_t)f * NTOK + n]);
        u64 hh = pack2(hf, hf);
        const ulonglong2* w = reinterpret_cast<const ulonglong2*>(sW2t + f*W2P);
#pragma unroll
        for (int i = 0; i < 16; i++) {
            ulonglong2 ww = w[i];
            y2[2*i]   = fma2(hh, ww.x, y2[2*i]);
            y2[2*i+1] = fma2(hh, ww.y, y2[2*i+1]);
        }
    }

    // LayerNorm over the 64 packed values
    u64 sacc = 0;
#pragma unroll
    for (int i = 0; i < 32; i++) sacc = add2(sacc, y2[i]);
    float slo, shi; unpack2(sacc, slo, shi);
    float m = (slo + shi) * (1.f/64.f);
    u64 mm = pack2(-m, -m);
    u64 vacc = 0;
#pragma unroll
    for (int i = 0; i < 32; i++) { u64 d = add2(y2[i], mm); vacc = fma2(d, d, vacc); }
    float vlo, vhi; unpack2(vacc, vlo, vhi);
    float rs = rsqrtf((vlo + vhi) * (1.f/64.f) + 1e-5f);

    float* op = out + (size_t)n * Ec;
#pragma unroll
    for (int i = 0; i < 16; i++) {
        float a,b,c,d;
        unpack2(y2[2*i], a, b); unpack2(y2[2*i+1], c, d);
        float4 v;
        v.x = (a - m) * rs * sg[4*i+0] + sbe[4*i+0];
        v.y = (b - m) * rs * sg[4*i+1] + sbe[4*i+1];
        v.z = (c - m) * rs * sg[4*i+2] + sbe[4*i+2];
        v.w = (d - m) * rs * sg[4*i+3] + sbe[4*i+3];
        reinterpret_cast<float4*>(op)[i] = v;
    }
#undef W2P
}

// ---------------------------------------------------------------------------
extern "C" void kernel_launch(void* const* d_in, const int* in_sizes, int n_in,
                              void* d_out, int out_size)
{
    const float* x     = (const float*)d_in[0];
    const float* Wq    = (const float*)d_in[1];
    const float* bq    = (const float*)d_in[2];
    const float* Wk    = (const float*)d_in[3];
    const float* bk    = (const float*)d_in[4];
    const float* Wv    = (const float*)d_in[5];
    const float* bv    = (const float*)d_in[6];
    const float* Wo    = (const float*)d_in[7];
    const float* bo    = (const float*)d_in[8];
    const float* th_a  = (const float*)d_in[9];
    const float* th_f  = (const float*)d_in[10];
    const float* W1    = (const float*)d_in[11];
    const float* b1    = (const float*)d_in[12];
    const float* W2    = (const float*)d_in[13];
    const float* b2    = (const float*)d_in[14];
    const float* g1    = (const float*)d_in[15];
    const float* be1   = (const float*)d_in[16];
    const float* g2    = (const float*)d_in[17];
    const float* be2   = (const float*)d_in[18];
    float* out = (float*)d_out;

    const size_t SM1 = (3*4096 + 192) * sizeof(float);          // 49,920 B
    const size_t SM2 = (size_t)2 * Tc * DKc * sizeof(float);    // 131,072 B
    const size_t SM3 = (4288 + 128*65) * sizeof(float);         // 50,432 B
    const size_t SM4a = (16384 + 256) * sizeof(float);          // 66,560 B
    const size_t SM4b = (256*68 + 192) * sizeof(float);         // 70,400 B

    cudaFuncSetAttribute(qkv_kernel,    cudaFuncAttributeMaxDynamicSharedMemorySize, (int)SM1);
    cudaFuncSetAttribute(attn_kernel,   cudaFuncAttributeMaxDynamicSharedMemorySize, (int)SM2);
    cudaFuncSetAttribute(oproj_kernel,  cudaFuncAttributeMaxDynamicSharedMemorySize, (int)SM3);
    cudaFuncSetAttribute(ffn_h_kernel,  cudaFuncAttributeMaxDynamicSharedMemorySize, (int)SM4a);
    cudaFuncSetAttribute(ffn_out_kernel,cudaFuncAttributeMaxDynamicSharedMemorySize, (int)SM4b);

    qkv_kernel<<<NTOK/128, 128, SM1>>>(x, Wq, bq, Wk, bk, Wv, bv, th_a);
    attn_kernel<<<dim3(Bc*Hc, Tc/128), 128, SM2>>>();
    oproj_kernel<<<NTOK/128, 128, SM3>>>(x, Wo, bo, g1, be1);
    ffn_h_kernel<<<NTOK/128, 128, SM4a>>>(W1, b1, th_f);
    ffn_out_kernel<<<NTOK/128, 128, SM4b>>>(W2, b2, g2, be2, out);
}

// round 4
// speedup vs baseline: 1.5325x; 1.5325x over previous
#include <cuda_runtime.h>
#include <math.h>

#define Bc   8
#define Tc   2048
#define Ec   64
#define Hc   8
#define DKc  8
#define FFc  256
#define NTOK (Bc*Tc)

typedef unsigned long long u64;

// ---- packed f32x2 helpers (sm_103a FFMA2; bit-exact fp32 per lane) ----
__device__ __forceinline__ u64 pack2(float lo, float hi) {
    u64 r; asm("mov.b64 %0,{%1,%2};" : "=l"(r) : "f"(lo), "f"(hi)); return r;
}
__device__ __forceinline__ void unpack2(u64 v, float& a, float& b) {
    asm("mov.b64 {%0,%1},%2;" : "=f"(a), "=f"(b) : "l"(v));
}
__device__ __forceinline__ u64 fma2(u64 a, u64 b, u64 c) {
    u64 d; asm("fma.rn.f32x2 %0,%1,%2,%3;" : "=l"(d) : "l"(a), "l"(b), "l"(c)); return d;
}
__device__ __forceinline__ u64 mul2(u64 a, u64 b) {
    u64 d; asm("mul.rn.f32x2 %0,%1,%2;" : "=l"(d) : "l"(a), "l"(b)); return d;
}
__device__ __forceinline__ u64 add2(u64 a, u64 b) {
    u64 d; asm("add.rn.f32x2 %0,%1,%2;" : "=l"(d) : "l"(a), "l"(b)); return d;
}

// Scratch (device globals)
__device__ float g_q[Bc*Hc*Tc*DKc];     // [b,h,t,d]
__device__ float g_k[Bc*Hc*Tc*DKc];
__device__ float g_v[Bc*Hc*Tc*DKc];
__device__ float g_attn[NTOK*Ec];       // [n, e], e = h*8+d
__device__ float g_x1[NTOK*Ec];
__device__ float g_h[(size_t)FFc*NTOK]; // f-major [f, n]

// ---------------------------------------------------------------------------
// K1: qkv. 128 threads, 64 tokens/CTA, 2 threads per token (4 heads each).
// grid = NTOK/64 = 256 CTAs -> 2 CTAs/SM, 8 warps/SM.
// ---------------------------------------------------------------------------
__global__ __launch_bounds__(128) void qkv_kernel(
    const float* __restrict__ x,
    const float* __restrict__ Wq, const float* __restrict__ bq,
    const float* __restrict__ Wk, const float* __restrict__ bk,
    const float* __restrict__ Wv, const float* __restrict__ bv,
    const float* __restrict__ theta_p)
{
    extern __shared__ float sm[];
    float* sWq = sm;
    float* sWk = sm + 4096;
    float* sWv = sm + 8192;
    float* sb  = sm + 12288;
    int tid = threadIdx.x;
    for (int i = tid; i < 4096; i += 128) { sWq[i] = Wq[i]; sWk[i] = Wk[i]; sWv[i] = Wv[i]; }
    if (tid < 64) { sb[tid] = bq[tid]; sb[64+tid] = bk[tid]; sb[128+tid] = bv[tid]; }
    __syncthreads();

    float theta = theta_p[0];
    int half = tid & 1;
    int n = blockIdx.x * 64 + (tid >> 1);

    u64 x2[32];
    const ulonglong2* xp = reinterpret_cast<const ulonglong2*>(x + (size_t)n * Ec);
#pragma unroll
    for (int i = 0; i < 16; i++) { ulonglong2 v = xp[i]; x2[2*i] = v.x; x2[2*i+1] = v.y; }

    int b = n >> 11, t = n & 2047;
    int base = b * (Hc*Tc*DKc) + t * DKc;

    for (int h = half*4; h < half*4 + 4; h++) {
        float q8[8], k8[8], v8[8];
#pragma unroll
        for (int d = 0; d < 8; d++) {
            int o = h*8 + d;
            const ulonglong2* wq = reinterpret_cast<const ulonglong2*>(sWq + o*64);
            const ulonglong2* wk = reinterpret_cast<const ulonglong2*>(sWk + o*64);
            const ulonglong2* wv = reinterpret_cast<const ulonglong2*>(sWv + o*64);
            u64 qa=0,qb_=0,ka=0,kb_=0,va=0,vb_=0;
#pragma unroll
            for (int i = 0; i < 16; i++) {
                ulonglong2 a = wq[i], c = wk[i], e = wv[i];
                qa  = fma2(x2[2*i], a.x, qa);  qb_ = fma2(x2[2*i+1], a.y, qb_);
                ka  = fma2(x2[2*i], c.x, ka);  kb_ = fma2(x2[2*i+1], c.y, kb_);
                va  = fma2(x2[2*i], e.x, va);  vb_ = fma2(x2[2*i+1], e.y, vb_);
            }
            float l0,h0,l1,h1,l2,h2;
            unpack2(add2(qa,qb_), l0, h0);
            unpack2(add2(ka,kb_), l1, h1);
            unpack2(add2(va,vb_), l2, h2);
            q8[d] = __cosf(l0 + h0 + sb[o]       + theta);
            k8[d] = __cosf(l1 + h1 + sb[64+o]    + theta);
            v8[d] = __cosf(l2 + h2 + sb[128+o]   + theta);
        }
        int off = base + h * (Tc*DKc);
        *reinterpret_cast<float4*>(g_q + off)     = make_float4(q8[0],q8[1],q8[2],q8[3]);
        *reinterpret_cast<float4*>(g_q + off + 4) = make_float4(q8[4],q8[5],q8[6],q8[7]);
        *reinterpret_cast<float4*>(g_k + off)     = make_float4(k8[0],k8[1],k8[2],k8[3]);
        *reinterpret_cast<float4*>(g_k + off + 4) = make_float4(k8[4],k8[5],k8[6],k8[7]);
        *reinterpret_cast<float4*>(g_v + off)     = make_float4(v8[0],v8[1],v8[2],v8[3]);
        *reinterpret_cast<float4*>(g_v + off + 4) = make_float4(v8[4],v8[5],v8[6],v8[7]);
    }
}

// ---------------------------------------------------------------------------
// K2: attention. 512 threads/CTA (16 warps -> 4 warps/SMSP), grid (64,4).
// f32x2 packed; bounded scores -> single-pass softmax, log2e folded into q.
// ---------------------------------------------------------------------------
__global__ __launch_bounds__(512) void attn_kernel()
{
    extern __shared__ float sm[];
    ulonglong2* K2s = reinterpret_cast<ulonglong2*>(sm);
    ulonglong2* V2s = reinterpret_cast<ulonglong2*>(sm + Tc*DKc);

    int bh  = blockIdx.x;   // 0..63
    int qt  = blockIdx.y;   // 0..3
    int tid = threadIdx.x;

    const ulonglong2* gk = reinterpret_cast<const ulonglong2*>(g_k + (size_t)bh * (Tc*DKc));
    const ulonglong2* gv = reinterpret_cast<const ulonglong2*>(g_v + (size_t)bh * (Tc*DKc));
    // K,V each 4096 ulonglong2; 512 threads x 8 iters
#pragma unroll
    for (int i = 0; i < 8; i++) {
        K2s[tid + 512*i] = gk[tid + 512*i];
        V2s[tid + 512*i] = gv[tid + 512*i];
    }
    __syncthreads();

    int t = qt * 512 + tid;
    const float* qp = g_q + (size_t)bh * (Tc*DKc) + t * DKc;
    const float QS = 0.35355339059327f * 1.4426950408889634f;  // 1/sqrt(8)*log2(e)
    u64 q01 = pack2(qp[0]*QS, qp[1]*QS);
    u64 q23 = pack2(qp[2]*QS, qp[3]*QS);
    u64 q45 = pack2(qp[4]*QS, qp[5]*QS);
    u64 q67 = pack2(qp[6]*QS, qp[7]*QS);

    float l = 0.f;
    u64 a01 = 0, a23 = 0, a45 = 0, a67 = 0;

    const ulonglong2* kp = K2s;
    const ulonglong2* vp = V2s;
#pragma unroll 8
    for (int j = 0; j < Tc; j++) {
        ulonglong2 ka = kp[0], kb = kp[1]; kp += 2;
        u64 d = mul2(q01, ka.x);
        d = fma2(q23, ka.y, d);
        d = fma2(q45, kb.x, d);
        d = fma2(q67, kb.y, d);
        float slo, shi; unpack2(d, slo, shi);
        float s = slo + shi;
        float p;
        asm("ex2.approx.f32 %0, %1;" : "=f"(p) : "f"(s));
        ulonglong2 va = vp[0], vb = vp[1]; vp += 2;
        u64 pp = pack2(p, p);
        l += p;
        a01 = fma2(pp, va.x, a01);
        a23 = fma2(pp, va.y, a23);
        a45 = fma2(pp, vb.x, a45);
        a67 = fma2(pp, vb.y, a67);
    }
    float inv = 1.0f / l;

    float o0,o1,o2,o3,o4,o5,o6,o7;
    unpack2(a01,o0,o1); unpack2(a23,o2,o3); unpack2(a45,o4,o5); unpack2(a67,o6,o7);
    int b = bh >> 3, h = bh & 7;
    float* op = g_attn + ((size_t)(b*Tc + t)) * Ec + h * DKc;
    reinterpret_cast<float4*>(op)[0] = make_float4(o0*inv, o1*inv, o2*inv, o3*inv);
    reinterpret_cast<float4*>(op)[1] = make_float4(o4*inv, o5*inv, o6*inv, o7*inv);
}

// ---------------------------------------------------------------------------
// K3: x1 = LN(x + attn @ Wo^T + bo). 2 threads/token: each computes 32 e's;
// LN sums combined via shfl_xor(1). grid 256 x 128 threads.
// ---------------------------------------------------------------------------
__global__ __launch_bounds__(128) void oproj_kernel(
    const float* __restrict__ x, const float* __restrict__ Wo,
    const float* __restrict__ bo, const float* __restrict__ g1,
    const float* __restrict__ be1)
{
    extern __shared__ float sm[];
    float* sWo = sm;              // 4096
    float* sbo = sm + 4096;
    float* sg  = sm + 4160;
    float* sbe = sm + 4224;
    int tid = threadIdx.x;
    for (int i = tid; i < 4096; i += 128) sWo[i] = Wo[i];
    if (tid < 64) { sbo[tid] = bo[tid]; sg[tid] = g1[tid]; sbe[tid] = be1[tid]; }
    __syncthreads();

    int half = tid & 1;
    int n = blockIdx.x * 64 + (tid >> 1);
    int e0 = half * 32;

    u64 a2[32];
    const ulonglong2* ap = reinterpret_cast<const ulonglong2*>(g_attn + (size_t)n * Ec);
#pragma unroll
    for (int i = 0; i < 16; i++) { ulonglong2 v = ap[i]; a2[2*i] = v.x; a2[2*i+1] = v.y; }

    float xr[32];
    const float4* xp = reinterpret_cast<const float4*>(x + (size_t)n * Ec + e0);
#pragma unroll
    for (int i = 0; i < 8; i++) {
        float4 v = xp[i];
        xr[4*i+0] = v.x; xr[4*i+1] = v.y; xr[4*i+2] = v.z; xr[4*i+3] = v.w;
    }

    float rr[32];
    float s1 = 0.f;
#pragma unroll 2
    for (int e = 0; e < 32; e++) {
        int ge = e0 + e;
        const ulonglong2* w = reinterpret_cast<const ulonglong2*>(sWo + ge*64);
        u64 c0 = 0, c1 = 0;
#pragma unroll
        for (int i = 0; i < 16; i++) {
            ulonglong2 ww = w[i];
            c0 = fma2(a2[2*i],   ww.x, c0);
            c1 = fma2(a2[2*i+1], ww.y, c1);
        }
        float lo, hi; unpack2(add2(c0, c1), lo, hi);
        float rv = xr[e] + lo + hi + sbo[ge];
        rr[e] = rv;
        s1 += rv;
    }
    s1 += __shfl_xor_sync(0xFFFFFFFFu, s1, 1);
    float m = s1 * (1.f/64.f);
    float s2 = 0.f;
#pragma unroll
    for (int e = 0; e < 32; e++) { float d = rr[e] - m; s2 = fmaf(d, d, s2); }
    s2 += __shfl_xor_sync(0xFFFFFFFFu, s2, 1);
    float rs = rsqrtf(s2 * (1.f/64.f) + 1e-5f);

    float* o = g_x1 + (size_t)n * Ec + e0;
#pragma unroll
    for (int i = 0; i < 8; i++) {
        float4 v;
        v.x = (rr[4*i+0] - m) * rs * sg[e0+4*i+0] + sbe[e0+4*i+0];
        v.y = (rr[4*i+1] - m) * rs * sg[e0+4*i+1] + sbe[e0+4*i+1];
        v.z = (rr[4*i+2] - m) * rs * sg[e0+4*i+2] + sbe[e0+4*i+2];
        v.w = (rr[4*i+3] - m) * rs * sg[e0+4*i+3] + sbe[e0+4*i+3];
        reinterpret_cast<float4*>(o)[i] = v;
    }
}

// ---------------------------------------------------------------------------
// K4a: H[f,n] = relu(cos(x1)*cos(theta) @ W1^T + b1). 2 threads/token,
// each does 128 of 256 f's. grid 256 x 128.
// ---------------------------------------------------------------------------
__global__ __launch_bounds__(128) void ffn_h_kernel(
    const float* __restrict__ W1, const float* __restrict__ b1,
    const float* __restrict__ theta_p)
{
    extern __shared__ float sm[];
    float* sW1 = sm;             // 16384
    float* sb1 = sm + 16384;     // 256
    int tid = threadIdx.x;
    for (int i = tid; i < 16384; i += 128) sW1[i] = W1[i];
    for (int i = tid; i < 256; i += 128) sb1[i] = b1[i];
    __syncthreads();

    float ct = __cosf(theta_p[0]);
    int half = tid & 1;
    int n = blockIdx.x * 64 + (tid >> 1);

    u64 qc[32];
    const ulonglong2* xp = reinterpret_cast<const ulonglong2*>(g_x1 + (size_t)n * Ec);
#pragma unroll
    for (int i = 0; i < 16; i++) {
        ulonglong2 v = xp[i];
        float a,b,c,d;
        unpack2(v.x, a, b); unpack2(v.y, c, d);
        qc[2*i]   = pack2(__cosf(a)*ct, __cosf(b)*ct);
        qc[2*i+1] = pack2(__cosf(c)*ct, __cosf(d)*ct);
    }

    int f0 = half * 128;
#pragma unroll 2
    for (int fi = 0; fi < 128; fi++) {
        int f = f0 + fi;
        const ulonglong2* w = reinterpret_cast<const ulonglong2*>(sW1 + f*64);
        u64 h0 = 0, h1 = 0;
#pragma unroll
        for (int i = 0; i < 16; i++) {
            ulonglong2 ww = w[i];
            h0 = fma2(qc[2*i],   ww.x, h0);
            h1 = fma2(qc[2*i+1], ww.y, h1);
        }
        float lo, hi; unpack2(add2(h0, h1), lo, hi);
        float hf = fmaxf(lo + hi + sb1[f], 0.f);
        g_h[(size_t)f * NTOK + n] = hf;
    }
}

// ---------------------------------------------------------------------------
// K4b: out = LN(x1 + H @ W2^T + b2). 2 threads/token: each accumulates 32 e's
// over all 256 f; LN combined via shfl. grid 256 x 128.
// ---------------------------------------------------------------------------
__global__ __launch_bounds__(128) void ffn_out_kernel(
    const float* __restrict__ W2, const float* __restrict__ b2,
    const float* __restrict__ g2, const float* __restrict__ be2,
    float* __restrict__ out)
{
#define W2P 68
    extern __shared__ float sm[];
    float* sW2t = sm;               // 256 * 68
    float* sb2  = sm + 256*W2P;
    float* sg   = sb2 + 64;
    float* sbe  = sg + 64;
    int tid = threadIdx.x;
    for (int i = tid; i < Ec*FFc; i += 128) {
        int e = i >> 8, f = i & 255;
        sW2t[f*W2P + e] = W2[i];
    }
    if (tid < 64) { sb2[tid] = b2[tid]; sg[tid] = g2[tid]; sbe[tid] = be2[tid]; }
    __syncthreads();

    int half = tid & 1;
    int n = blockIdx.x * 64 + (tid >> 1);
    int e0 = half * 32;

    u64 y2[16];
    const ulonglong2* xp = reinterpret_cast<const ulonglong2*>(g_x1 + (size_t)n * Ec + e0);
#pragma unroll
    for (int i = 0; i < 8; i++) {
        ulonglong2 v = xp[i];
        float a,b,c,d;
        unpack2(v.x, a, b); unpack2(v.y, c, d);
        y2[2*i]   = pack2(a + sb2[e0+4*i+0], b + sb2[e0+4*i+1]);
        y2[2*i+1] = pack2(c + sb2[e0+4*i+2], d + sb2[e0+4*i+3]);
    }

#pragma unroll 4
    for (int f = 0; f < FFc; f++) {
        float hf = __ldg(&g_h[(size_t)f * NTOK + n]);
        u64 hh = pack2(hf, hf);
        const ulonglong2* w = reinterpret_cast<const ulonglong2*>(sW2t + f*W2P + e0);
#pragma unroll
        for (int i = 0; i < 8; i++) {
            ulonglong2 ww = w[i];
            y2[2*i]   = fma2(hh, ww.x, y2[2*i]);
            y2[2*i+1] = fma2(hh, ww.y, y2[2*i+1]);
        }
    }

    u64 sacc = 0;
#pragma unroll
    for (int i = 0; i < 16; i++) sacc = add2(sacc, y2[i]);
    float slo, shi; unpack2(sacc, slo, shi);
    float s1 = slo + shi;
    s1 += __shfl_xor_sync(0xFFFFFFFFu, s1, 1);
    float m = s1 * (1.f/64.f);
    u64 mm = pack2(-m, -m);
    u64 vacc = 0;
#pragma unroll
    for (int i = 0; i < 16; i++) { u64 d = add2(y2[i], mm); vacc = fma2(d, d, vacc); }
    float vlo, vhi; unpack2(vacc, vlo, vhi);
    float s2 = vlo + vhi;
    s2 += __shfl_xor_sync(0xFFFFFFFFu, s2, 1);
    float rs = rsqrtf(s2 * (1.f/64.f) + 1e-5f);

    float* op = out + (size_t)n * Ec + e0;
#pragma unroll
    for (int i = 0; i < 8; i++) {
        float a,b,c,d;
        unpack2(y2[2*i], a, b); unpack2(y2[2*i+1], c, d);
        float4 v;
        v.x = (a - m) * rs * sg[e0+4*i+0] + sbe[e0+4*i+0];
        v.y = (b - m) * rs * sg[e0+4*i+1] + sbe[e0+4*i+1];
        v.z = (c - m) * rs * sg[e0+4*i+2] + sbe[e0+4*i+2];
        v.w = (d - m) * rs * sg[e0+4*i+3] + sbe[e0+4*i+3];
        reinterpret_cast<float4*>(op)[i] = v;
    }
#undef W2P
}

// ---------------------------------------------------------------------------
extern "C" void kernel_launch(void* const* d_in, const int* in_sizes, int n_in,
                              void* d_out, int out_size)
{
    const float* x     = (const float*)d_in[0];
    const float* Wq    = (const float*)d_in[1];
    const float* bq    = (const float*)d_in[2];
    const float* Wk    = (const float*)d_in[3];
    const float* bk    = (const float*)d_in[4];
    const float* Wv    = (const float*)d_in[5];
    const float* bv    = (const float*)d_in[6];
    const float* Wo    = (const float*)d_in[7];
    const float* bo    = (const float*)d_in[8];
    const float* th_a  = (const float*)d_in[9];
    const float* th_f  = (const float*)d_in[10];
    const float* W1    = (const float*)d_in[11];
    const float* b1    = (const float*)d_in[12];
    const float* W2    = (const float*)d_in[13];
    const float* b2    = (const float*)d_in[14];
    const float* g1    = (const float*)d_in[15];
    const float* be1   = (const float*)d_in[16];
    const float* g2    = (const float*)d_in[17];
    const float* be2   = (const float*)d_in[18];
    float* out = (float*)d_out;

    const size_t SM1 = (3*4096 + 192) * sizeof(float);          // 49,920 B
    const size_t SM2 = (size_t)2 * Tc * DKc * sizeof(float);    // 131,072 B
    const size_t SM3 = (4096 + 192) * sizeof(float);            // 17,152 B
    const size_t SM4a = (16384 + 256) * sizeof(float);          // 66,560 B
    const size_t SM4b = (256*68 + 192) * sizeof(float);         // 70,400 B

    cudaFuncSetAttribute(qkv_kernel,    cudaFuncAttributeMaxDynamicSharedMemorySize, (int)SM1);
    cudaFuncSetAttribute(attn_kernel,   cudaFuncAttributeMaxDynamicSharedMemorySize, (int)SM2);
    cudaFuncSetAttribute(oproj_kernel,  cudaFuncAttributeMaxDynamicSharedMemorySize, (int)SM3);
    cudaFuncSetAttribute(ffn_h_kernel,  cudaFuncAttributeMaxDynamicSharedMemorySize, (int)SM4a);
    cudaFuncSetAttribute(ffn_out_kernel,cudaFuncAttributeMaxDynamicSharedMemorySize, (int)SM4b);

    qkv_kernel<<<NTOK/64, 128, SM1>>>(x, Wq, bq, Wk, bk, Wv, bv, th_a);
    attn_kernel<<<dim3(Bc*Hc, Tc/512), 512, SM2>>>();
    oproj_kernel<<<NTOK/64, 128, SM3>>>(x, Wo, bo, g1, be1);
    ffn_h_kernel<<<NTOK/64, 128, SM4a>>>(W1, b1, th_f);
    ffn_out_kernel<<<NTOK/64, 128, SM4b>>>(W2, b2, g2, be2, out);
}

// round 5
// speedup vs baseline: 1.6399x; 1.0701x over previous
#include <cuda_runtime.h>
#include <math.h>

#define Bc   8
#define Tc   2048
#define Ec   64
#define Hc   8
#define DKc  8
#define FFc  256
#define NTOK (Bc*Tc)

typedef unsigned long long u64;

// ---- packed f32x2 helpers (bit-exact fp32 per lane) ----
__device__ __forceinline__ u64 pack2(float lo, float hi) {
    u64 r; asm("mov.b64 %0,{%1,%2};" : "=l"(r) : "f"(lo), "f"(hi)); return r;
}
__device__ __forceinline__ u64 dup2(float v) {
    u64 r; asm("mov.b64 %0,{%1,%1};" : "=l"(r) : "f"(v)); return r;
}
__device__ __forceinline__ void unpack2(u64 v, float& a, float& b) {
    asm("mov.b64 {%0,%1},%2;" : "=f"(a), "=f"(b) : "l"(v));
}
__device__ __forceinline__ u64 fma2(u64 a, u64 b, u64 c) {
    u64 d; asm("fma.rn.f32x2 %0,%1,%2,%3;" : "=l"(d) : "l"(a), "l"(b), "l"(c)); return d;
}
__device__ __forceinline__ u64 mul2(u64 a, u64 b) {
    u64 d; asm("mul.rn.f32x2 %0,%1,%2;" : "=l"(d) : "l"(a), "l"(b)); return d;
}
__device__ __forceinline__ u64 add2(u64 a, u64 b) {
    u64 d; asm("add.rn.f32x2 %0,%1,%2;" : "=l"(d) : "l"(a), "l"(b)); return d;
}
__device__ __forceinline__ float ex2f(float s) {
    float p; asm("ex2.approx.f32 %0,%1;" : "=f"(p) : "f"(s)); return p;
}

// Scratch (device globals)
__device__ float g_q[Bc*Hc*Tc*DKc];     // [b,h,t,d]
__device__ float g_k[Bc*Hc*Tc*DKc];
__device__ float g_v[Bc*Hc*Tc*DKc];
__device__ float g_attn[NTOK*Ec];       // [n, e], e = h*8+d
__device__ float g_x1[NTOK*Ec];
__device__ float g_h[(size_t)FFc*NTOK]; // f-major [f, n]

// =====================================================================
// K1: qkv. GEMM-tiled: 128 tokens x 192 outs per block, 256 threads.
// Thread tile: 8 tokens (4 f32x2 pairs) x 4 outs. q/k/v processed
// sequentially reusing xT in smem. cos(.+b+theta) in epilogue.
// =====================================================================
__global__ __launch_bounds__(256) void qkv_kernel(
    const float* __restrict__ x,
    const float* __restrict__ Wq, const float* __restrict__ bq,
    const float* __restrict__ Wk, const float* __restrict__ bk,
    const float* __restrict__ Wv, const float* __restrict__ bv,
    const float* __restrict__ theta_p)
{
    extern __shared__ float sm[];
    float* xT  = sm;                 // [64][132] = 8448
    float* wTq = sm + 8448;          // [64][68]  = 4352
    float* wTk = wTq + 4352;
    float* wTv = wTk + 4352;
    float* sb  = wTv + 4352;         // 192
    int tid = threadIdx.x;

    for (int i = tid; i < 4096; i += 256) {
        int o = i >> 6, k = i & 63;
        wTq[k*68+o] = Wq[i]; wTk[k*68+o] = Wk[i]; wTv[k*68+o] = Wv[i];
    }
    if (tid < 64) { sb[tid] = bq[tid]; sb[64+tid] = bk[tid]; sb[128+tid] = bv[tid]; }

    int n0 = blockIdx.x * 128;
    const float4* xsrc = reinterpret_cast<const float4*>(x + (size_t)n0 * Ec);
    for (int i = tid; i < 2048; i += 256) {
        int r = i >> 4, eg = i & 15;
        float4 v = xsrc[i];
        xT[(eg*4+0)*132 + r] = v.x;
        xT[(eg*4+1)*132 + r] = v.y;
        xT[(eg*4+2)*132 + r] = v.z;
        xT[(eg*4+3)*132 + r] = v.w;
    }
    __syncthreads();

    float theta = theta_p[0];
    int tokg = tid & 15, outg = tid >> 4;
    int b = n0 >> 11;
    int tt0 = (n0 & 2047) + tokg * 8;
    int o0 = outg * 4, h = o0 >> 3, d0 = o0 & 7;

    const float* wTs[3] = { wTq, wTk, wTv };
    float* gouts[3];
    gouts[0] = g_q; gouts[1] = g_k; gouts[2] = g_v;

#pragma unroll
    for (int m = 0; m < 3; m++) {
        const float* wT = wTs[m];
        const float* bias = sb + m*64;
        float* gout = gouts[m];
        u64 acc[4][4];
#pragma unroll
        for (int a = 0; a < 4; a++)
#pragma unroll
            for (int j = 0; j < 4; j++) acc[a][j] = 0;

#pragma unroll 4
        for (int k = 0; k < 64; k++) {
            const ulonglong2* xr = reinterpret_cast<const ulonglong2*>(xT + k*132 + tokg*8);
            ulonglong2 xa = xr[0], xb = xr[1];
            float4 wv = *reinterpret_cast<const float4*>(wT + k*68 + o0);
            u64 w0 = dup2(wv.x), w1 = dup2(wv.y), w2 = dup2(wv.z), w3 = dup2(wv.w);
            acc[0][0]=fma2(xa.x,w0,acc[0][0]); acc[0][1]=fma2(xa.x,w1,acc[0][1]);
            acc[0][2]=fma2(xa.x,w2,acc[0][2]); acc[0][3]=fma2(xa.x,w3,acc[0][3]);
            acc[1][0]=fma2(xa.y,w0,acc[1][0]); acc[1][1]=fma2(xa.y,w1,acc[1][1]);
            acc[1][2]=fma2(xa.y,w2,acc[1][2]); acc[1][3]=fma2(xa.y,w3,acc[1][3]);
            acc[2][0]=fma2(xb.x,w0,acc[2][0]); acc[2][1]=fma2(xb.x,w1,acc[2][1]);
            acc[2][2]=fma2(xb.x,w2,acc[2][2]); acc[2][3]=fma2(xb.x,w3,acc[2][3]);
            acc[3][0]=fma2(xb.y,w0,acc[3][0]); acc[3][1]=fma2(xb.y,w1,acc[3][1]);
            acc[3][2]=fma2(xb.y,w2,acc[3][2]); acc[3][3]=fma2(xb.y,w3,acc[3][3]);
        }
        float bb0 = bias[o0+0]+theta, bb1 = bias[o0+1]+theta,
              bb2 = bias[o0+2]+theta, bb3 = bias[o0+3]+theta;
        size_t gbase = ((size_t)b*Hc + h) * (Tc*DKc) + d0;
#pragma unroll
        for (int tp = 0; tp < 4; tp++) {
            float v00,v10, v01,v11, v02,v12, v03,v13;
            unpack2(acc[tp][0], v00, v10);
            unpack2(acc[tp][1], v01, v11);
            unpack2(acc[tp][2], v02, v12);
            unpack2(acc[tp][3], v03, v13);
            int t0 = tt0 + tp*2;
            float4 r0 = make_float4(__cosf(v00+bb0), __cosf(v01+bb1), __cosf(v02+bb2), __cosf(v03+bb3));
            float4 r1 = make_float4(__cosf(v10+bb0), __cosf(v11+bb1), __cosf(v12+bb2), __cosf(v13+bb3));
            *reinterpret_cast<float4*>(gout + gbase + (size_t)t0*8)     = r0;
            *reinterpret_cast<float4*>(gout + gbase + (size_t)(t0+1)*8) = r1;
        }
        __syncthreads();   // harmless; keeps wT reads coherent per matrix
    }
}

// =====================================================================
// K2: attention. 512 threads (4 warps/SMSP), grid (64,4).
// Paired-key K layout: K2p[j/2][d] = (k_j[d], k_{j+1}[d]) -> per-lane
// complete dot products, no horizontal add. 17 fma-pipe ops / 2 keys.
// =====================================================================
__global__ __launch_bounds__(512) void attn_kernel()
{
    extern __shared__ float sm[];
    u64* K2p = reinterpret_cast<u64*>(sm);            // [1024][8]  64KB
    u64* V2  = reinterpret_cast<u64*>(sm + 16384);    // [2048][4]  64KB

    int bh  = blockIdx.x;
    int qt  = blockIdx.y;
    int tid = threadIdx.x;

    const float* gk = g_k + (size_t)bh * (Tc*DKc);
#pragma unroll
    for (int i = tid; i < 8192; i += 512) {
        int j2 = i >> 3, d = i & 7;
        K2p[i] = pack2(gk[j2*16 + d], gk[j2*16 + 8 + d]);
    }
    const ulonglong2* gv = reinterpret_cast<const ulonglong2*>(g_v + (size_t)bh * (Tc*DKc));
    ulonglong2* V4 = reinterpret_cast<ulonglong2*>(V2);
#pragma unroll
    for (int i = 0; i < 8; i++) V4[tid + 512*i] = gv[tid + 512*i];
    __syncthreads();

    int t = qt * 512 + tid;
    const float* qp = g_q + (size_t)bh * (Tc*DKc) + t * DKc;
    const float QS = 0.35355339059327f * 1.4426950408889634f;  // 1/sqrt(8)*log2(e)
    u64 qd[8];
#pragma unroll
    for (int d = 0; d < 8; d++) { float qv = qp[d]*QS; qd[d] = dup2(qv); }

    u64 l2 = 0, a01 = 0, a23 = 0, a45 = 0, a67 = 0;
    const ulonglong2* kp = reinterpret_cast<const ulonglong2*>(K2p);
    const ulonglong2* vp = reinterpret_cast<const ulonglong2*>(V2);

#pragma unroll 4
    for (int j2 = 0; j2 < 1024; j2++) {
        ulonglong2 kA = kp[0], kB = kp[1], kC = kp[2], kD = kp[3]; kp += 4;
        u64 s2 = mul2(qd[0], kA.x);
        s2 = fma2(qd[1], kA.y, s2);
        s2 = fma2(qd[2], kB.x, s2);
        s2 = fma2(qd[3], kB.y, s2);
        s2 = fma2(qd[4], kC.x, s2);
        s2 = fma2(qd[5], kC.y, s2);
        s2 = fma2(qd[6], kD.x, s2);
        s2 = fma2(qd[7], kD.y, s2);
        float s0, s1; unpack2(s2, s0, s1);
        float p0 = ex2f(s0), p1 = ex2f(s1);
        ulonglong2 vA = vp[0], vB = vp[1], vC = vp[2], vD = vp[3]; vp += 4;
        u64 pp0 = dup2(p0), pp1 = dup2(p1);
        l2 = add2(l2, pack2(p0, p1));
        a01 = fma2(pp0, vA.x, a01); a23 = fma2(pp0, vA.y, a23);
        a45 = fma2(pp0, vB.x, a45); a67 = fma2(pp0, vB.y, a67);
        a01 = fma2(pp1, vC.x, a01); a23 = fma2(pp1, vC.y, a23);
        a45 = fma2(pp1, vD.x, a45); a67 = fma2(pp1, vD.y, a67);
    }
    float llo, lhi; unpack2(l2, llo, lhi);
    float inv = 1.0f / (llo + lhi);

    float o0,o1,o2,o3,o4,o5,o6,o7;
    unpack2(a01,o0,o1); unpack2(a23,o2,o3); unpack2(a45,o4,o5); unpack2(a67,o6,o7);
    int b = bh >> 3, h = bh & 7;
    float* op = g_attn + ((size_t)(b*Tc + t)) * Ec + h * DKc;
    reinterpret_cast<float4*>(op)[0] = make_float4(o0*inv, o1*inv, o2*inv, o3*inv);
    reinterpret_cast<float4*>(op)[1] = make_float4(o4*inv, o5*inv, o6*inv, o7*inv);
}

// =====================================================================
// K3: oproj + LN.  GEMM tile 128 tok x 64 out, 256 threads;
// LN via smem partial sums (pitch 17).
// =====================================================================
__global__ __launch_bounds__(256) void oproj_kernel(
    const float* __restrict__ x, const float* __restrict__ Wo,
    const float* __restrict__ bo, const float* __restrict__ g1,
    const float* __restrict__ be1)
{
    extern __shared__ float sm[];
    float* xT   = sm;             // [64][132] = 8448
    float* wT   = sm + 8448;      // [64][68]  = 4352
    float* sbo  = wT + 4352;      // 64
    float* sg   = sbo + 64;       // 64
    float* sbe  = sg + 64;        // 64
    float* red1 = sbe + 64;       // 128*17 = 2176
    float* red2 = red1 + 2176;    // 2176
    float* mS   = red2 + 2176;    // 128
    float* rsS  = mS + 128;       // 128
    int tid = threadIdx.x;

    for (int i = tid; i < 4096; i += 256) {
        int o = i >> 6, k = i & 63;
        wT[k*68+o] = Wo[i];
    }
    if (tid < 64) { sbo[tid] = bo[tid]; sg[tid] = g1[tid]; sbe[tid] = be1[tid]; }

    int n0 = blockIdx.x * 128;
    const float4* asrc = reinterpret_cast<const float4*>(g_attn + (size_t)n0 * Ec);
    for (int i = tid; i < 2048; i += 256) {
        int r = i >> 4, eg = i & 15;
        float4 v = asrc[i];
        xT[(eg*4+0)*132 + r] = v.x;
        xT[(eg*4+1)*132 + r] = v.y;
        xT[(eg*4+2)*132 + r] = v.z;
        xT[(eg*4+3)*132 + r] = v.w;
    }
    __syncthreads();

    int tokg = tid & 15, outg = tid >> 4;
    int o0 = outg * 4;

    u64 acc[4][4];
#pragma unroll
    for (int a = 0; a < 4; a++)
#pragma unroll
        for (int j = 0; j < 4; j++) acc[a][j] = 0;

#pragma unroll 4
    for (int k = 0; k < 64; k++) {
        const ulonglong2* xr = reinterpret_cast<const ulonglong2*>(xT + k*132 + tokg*8);
        ulonglong2 xa = xr[0], xb = xr[1];
        float4 wv = *reinterpret_cast<const float4*>(wT + k*68 + o0);
        u64 w0 = dup2(wv.x), w1 = dup2(wv.y), w2 = dup2(wv.z), w3 = dup2(wv.w);
        acc[0][0]=fma2(xa.x,w0,acc[0][0]); acc[0][1]=fma2(xa.x,w1,acc[0][1]);
        acc[0][2]=fma2(xa.x,w2,acc[0][2]); acc[0][3]=fma2(xa.x,w3,acc[0][3]);
        acc[1][0]=fma2(xa.y,w0,acc[1][0]); acc[1][1]=fma2(xa.y,w1,acc[1][1]);
        acc[1][2]=fma2(xa.y,w2,acc[1][2]); acc[1][3]=fma2(xa.y,w3,acc[1][3]);
        acc[2][0]=fma2(xb.x,w0,acc[2][0]); acc[2][1]=fma2(xb.x,w1,acc[2][1]);
        acc[2][2]=fma2(xb.x,w2,acc[2][2]); acc[2][3]=fma2(xb.x,w3,acc[2][3]);
        acc[3][0]=fma2(xb.y,w0,acc[3][0]); acc[3][1]=fma2(xb.y,w1,acc[3][1]);
        acc[3][2]=fma2(xb.y,w2,acc[3][2]); acc[3][3]=fma2(xb.y,w3,acc[3][3]);
    }

    float bb0 = sbo[o0+0], bb1 = sbo[o0+1], bb2 = sbo[o0+2], bb3 = sbo[o0+3];
    float y[8][4];
#pragma unroll
    for (int tp = 0; tp < 4; tp++) {
        int lt = tokg*8 + tp*2;
        float4 r0 = *reinterpret_cast<const float4*>(x + (size_t)(n0+lt)   * Ec + o0);
        float4 r1 = *reinterpret_cast<const float4*>(x + (size_t)(n0+lt+1) * Ec + o0);
        float v0,v1;
        unpack2(acc[tp][0], v0, v1); y[tp*2][0] = v0 + r0.x + bb0; y[tp*2+1][0] = v1 + r1.x + bb0;
        unpack2(acc[tp][1], v0, v1); y[tp*2][1] = v0 + r0.y + bb1; y[tp*2+1][1] = v1 + r1.y + bb1;
        unpack2(acc[tp][2], v0, v1); y[tp*2][2] = v0 + r0.z + bb2; y[tp*2+1][2] = v1 + r1.z + bb2;
        unpack2(acc[tp][3], v0, v1); y[tp*2][3] = v0 + r0.w + bb3; y[tp*2+1][3] = v1 + r1.w + bb3;
    }
#pragma unroll
    for (int i = 0; i < 8; i++) {
        int lt = tokg*8 + i;
        float s1 = y[i][0]+y[i][1]+y[i][2]+y[i][3];
        float s2 = y[i][0]*y[i][0]+y[i][1]*y[i][1]+y[i][2]*y[i][2]+y[i][3]*y[i][3];
        red1[lt*17 + outg] = s1;
        red2[lt*17 + outg] = s2;
    }
    __syncthreads();
    if (tid < 128) {
        float s1 = 0.f, s2 = 0.f;
#pragma unroll
        for (int o = 0; o < 16; o++) { s1 += red1[tid*17+o]; s2 += red2[tid*17+o]; }
        float m = s1 * (1.f/64.f);
        float var = s2 * (1.f/64.f) - m*m;
        mS[tid] = m;
        rsS[tid] = rsqrtf(var + 1e-5f);
    }
    __syncthreads();

    float gg0 = sg[o0+0], gg1 = sg[o0+1], gg2 = sg[o0+2], gg3 = sg[o0+3];
    float ee0 = sbe[o0+0], ee1 = sbe[o0+1], ee2 = sbe[o0+2], ee3 = sbe[o0+3];
#pragma unroll
    for (int i = 0; i < 8; i++) {
        int lt = tokg*8 + i;
        float m = mS[lt], rs = rsS[lt];
        float4 v;
        v.x = (y[i][0]-m)*rs*gg0 + ee0;
        v.y = (y[i][1]-m)*rs*gg1 + ee1;
        v.z = (y[i][2]-m)*rs*gg2 + ee2;
        v.w = (y[i][3]-m)*rs*gg3 + ee3;
        *reinterpret_cast<float4*>(g_x1 + (size_t)(n0+lt) * Ec + o0) = v;
    }
}

// =====================================================================
// K4a: H[f,n] = relu(cos(x1)*ct @ W1^T + b1). GEMM tile 128 tok x 64 f,
// 4 output passes reusing xT (cos applied at transpose-load).
// =====================================================================
__global__ __launch_bounds__(256) void ffn_h_kernel(
    const float* __restrict__ W1, const float* __restrict__ b1,
    const float* __restrict__ theta_p)
{
    extern __shared__ float sm[];
    float* xT  = sm;             // [64][132] = 8448
    float* w1T = sm + 8448;      // [64][260] = 16640
    float* sb1 = w1T + 16640;    // 256
    int tid = threadIdx.x;

    for (int i = tid; i < 16384; i += 256) {
        int f = i >> 6, k = i & 63;
        w1T[k*260 + f] = W1[i];
    }
    if (tid < 256) sb1[tid] = b1[tid];

    float ct = __cosf(theta_p[0]);
    int n0 = blockIdx.x * 128;
    const float4* xsrc = reinterpret_cast<const float4*>(g_x1 + (size_t)n0 * Ec);
    for (int i = tid; i < 2048; i += 256) {
        int r = i >> 4, eg = i & 15;
        float4 v = xsrc[i];
        xT[(eg*4+0)*132 + r] = __cosf(v.x)*ct;
        xT[(eg*4+1)*132 + r] = __cosf(v.y)*ct;
        xT[(eg*4+2)*132 + r] = __cosf(v.z)*ct;
        xT[(eg*4+3)*132 + r] = __cosf(v.w)*ct;
    }
    __syncthreads();

    int tokg = tid & 15, outg = tid >> 4;

#pragma unroll
    for (int fpass = 0; fpass < 4; fpass++) {
        int f0 = fpass*64 + outg*4;
        u64 acc[4][4];
#pragma unroll
        for (int a = 0; a < 4; a++)
#pragma unroll
            for (int j = 0; j < 4; j++) acc[a][j] = 0;

#pragma unroll 4
        for (int k = 0; k < 64; k++) {
            const ulonglong2* xr = reinterpret_cast<const ulonglong2*>(xT + k*132 + tokg*8);
            ulonglong2 xa = xr[0], xb = xr[1];
            float4 wv = *reinterpret_cast<const float4*>(w1T + k*260 + f0);
            u64 w0 = dup2(wv.x), w1 = dup2(wv.y), w2 = dup2(wv.z), w3 = dup2(wv.w);
            acc[0][0]=fma2(xa.x,w0,acc[0][0]); acc[0][1]=fma2(xa.x,w1,acc[0][1]);
            acc[0][2]=fma2(xa.x,w2,acc[0][2]); acc[0][3]=fma2(xa.x,w3,acc[0][3]);
            acc[1][0]=fma2(xa.y,w0,acc[1][0]); acc[1][1]=fma2(xa.y,w1,acc[1][1]);
            acc[1][2]=fma2(xa.y,w2,acc[1][2]); acc[1][3]=fma2(xa.y,w3,acc[1][3]);
            acc[2][0]=fma2(xb.x,w0,acc[2][0]); acc[2][1]=fma2(xb.x,w1,acc[2][1]);
            acc[2][2]=fma2(xb.x,w2,acc[2][2]); acc[2][3]=fma2(xb.x,w3,acc[2][3]);
            acc[3][0]=fma2(xb.y,w0,acc[3][0]); acc[3][1]=fma2(xb.y,w1,acc[3][1]);
            acc[3][2]=fma2(xb.y,w2,acc[3][2]); acc[3][3]=fma2(xb.y,w3,acc[3][3]);
        }
#pragma unroll
        for (int j = 0; j < 4; j++) {
            int f = f0 + j;
            float bb = sb1[f];
            float v0,v1,v2,v3,v4,v5,v6,v7;
            unpack2(acc[0][j], v0, v1);
            unpack2(acc[1][j], v2, v3);
            unpack2(acc[2][j], v4, v5);
            unpack2(acc[3][j], v6, v7);
            float4 h0 = make_float4(fmaxf(v0+bb,0.f), fmaxf(v1+bb,0.f),
                                    fmaxf(v2+bb,0.f), fmaxf(v3+bb,0.f));
            float4 h1 = make_float4(fmaxf(v4+bb,0.f), fmaxf(v5+bb,0.f),
                                    fmaxf(v6+bb,0.f), fmaxf(v7+bb,0.f));
            float* hp = g_h + (size_t)f * NTOK + n0 + tokg*8;
            reinterpret_cast<float4*>(hp)[0] = h0;
            reinterpret_cast<float4*>(hp)[1] = h1;
        }
    }
}

// =====================================================================
// K4b: out = LN(x1 + H @ W2^T + b2). K=256; H already k-major in gmem,
// streamed via LDG. W2^T in smem. LN as in oproj.
// =====================================================================
__global__ __launch_bounds__(256) void ffn_out_kernel(
    const float* __restrict__ W2, const float* __restrict__ b2,
    const float* __restrict__ g2, const float* __restrict__ be2,
    float* __restrict__ out)
{
    extern __shared__ float sm[];
    float* w2T  = sm;             // [256][68] = 17408
    float* sb2  = sm + 17408;     // 64
    float* sg   = sb2 + 64;
    float* sbe  = sg + 64;
    float* red1 = sbe + 64;       // 2176
    float* red2 = red1 + 2176;
    float* mS   = red2 + 2176;    // 128
    float* rsS  = mS + 128;
    int tid = threadIdx.x;

    for (int i = tid; i < Ec*FFc; i += 256) {
        int e = i >> 8, f = i & 255;
        w2T[f*68 + e] = W2[i];
    }
    if (tid < 64) { sb2[tid] = b2[tid]; sg[tid] = g2[tid]; sbe[tid] = be2[tid]; }
    __syncthreads();

    int n0 = blockIdx.x * 128;
    int tokg = tid & 15, outg = tid >> 4;
    int o0 = outg * 4;

    u64 acc[4][4];
#pragma unroll
    for (int a = 0; a < 4; a++)
#pragma unroll
        for (int j = 0; j < 4; j++) acc[a][j] = 0;

#pragma unroll 4
    for (int k = 0; k < 256; k++) {
        const ulonglong2* hp = reinterpret_cast<const ulonglong2*>(g_h + (size_t)k * NTOK + n0 + tokg*8);
        ulonglong2 xa = hp[0], xb = hp[1];
        float4 wv = *reinterpret_cast<const float4*>(w2T + k*68 + o0);
        u64 w0 = dup2(wv.x), w1 = dup2(wv.y), w2_ = dup2(wv.z), w3 = dup2(wv.w);
        acc[0][0]=fma2(xa.x,w0,acc[0][0]); acc[0][1]=fma2(xa.x,w1,acc[0][1]);
        acc[0][2]=fma2(xa.x,w2_,acc[0][2]); acc[0][3]=fma2(xa.x,w3,acc[0][3]);
        acc[1][0]=fma2(xa.y,w0,acc[1][0]); acc[1][1]=fma2(xa.y,w1,acc[1][1]);
        acc[1][2]=fma2(xa.y,w2_,acc[1][2]); acc[1][3]=fma2(xa.y,w3,acc[1][3]);
        acc[2][0]=fma2(xb.x,w0,acc[2][0]); acc[2][1]=fma2(xb.x,w1,acc[2][1]);
        acc[2][2]=fma2(xb.x,w2_,acc[2][2]); acc[2][3]=fma2(xb.x,w3,acc[2][3]);
        acc[3][0]=fma2(xb.y,w0,acc[3][0]); acc[3][1]=fma2(xb.y,w1,acc[3][1]);
        acc[3][2]=fma2(xb.y,w2_,acc[3][2]); acc[3][3]=fma2(xb.y,w3,acc[3][3]);
    }

    float bb0 = sb2[o0+0], bb1 = sb2[o0+1], bb2v = sb2[o0+2], bb3 = sb2[o0+3];
    float y[8][4];
#pragma unroll
    for (int tp = 0; tp < 4; tp++) {
        int lt = tokg*8 + tp*2;
        float4 r0 = *reinterpret_cast<const float4*>(g_x1 + (size_t)(n0+lt)   * Ec + o0);
        float4 r1 = *reinterpret_cast<const float4*>(g_x1 + (size_t)(n0+lt+1) * Ec + o0);
        float v0,v1;
        unpack2(acc[tp][0], v0, v1); y[tp*2][0] = v0 + r0.x + bb0; y[tp*2+1][0] = v1 + r1.x + bb0;
        unpack2(acc[tp][1], v0, v1); y[tp*2][1] = v0 + r0.y + bb1; y[tp*2+1][1] = v1 + r1.y + bb1;
        unpack2(acc[tp][2], v0, v1); y[tp*2][2] = v0 + r0.z + bb2v; y[tp*2+1][2] = v1 + r1.z + bb2v;
        unpack2(acc[tp][3], v0, v1); y[tp*2][3] = v0 + r0.w + bb3; y[tp*2+1][3] = v1 + r1.w + bb3;
    }
#pragma unroll
    for (int i = 0; i < 8; i++) {
        int lt = tokg*8 + i;
        float s1 = y[i][0]+y[i][1]+y[i][2]+y[i][3];
        float s2 = y[i][0]*y[i][0]+y[i][1]*y[i][1]+y[i][2]*y[i][2]+y[i][3]*y[i][3];
        red1[lt*17 + outg] = s1;
        red2[lt*17 + outg] = s2;
    }
    __syncthreads();
    if (tid < 128) {
        float s1 = 0.f, s2 = 0.f;
#pragma unroll
        for (int o = 0; o < 16; o++) { s1 += red1[tid*17+o]; s2 += red2[tid*17+o]; }
        float m = s1 * (1.f/64.f);
        float var = s2 * (1.f/64.f) - m*m;
        mS[tid] = m;
        rsS[tid] = rsqrtf(var + 1e-5f);
    }
    __syncthreads();

    float gg0 = sg[o0+0], gg1 = sg[o0+1], gg2 = sg[o0+2], gg3 = sg[o0+3];
    float ee0 = sbe[o0+0], ee1 = sbe[o0+1], ee2 = sbe[o0+2], ee3 = sbe[o0+3];
#pragma unroll
    for (int i = 0; i < 8; i++) {
        int lt = tokg*8 + i;
        float m = mS[lt], rs = rsS[lt];
        float4 v;
        v.x = (y[i][0]-m)*rs*gg0 + ee0;
        v.y = (y[i][1]-m)*rs*gg1 + ee1;
        v.z = (y[i][2]-m)*rs*gg2 + ee2;
        v.w = (y[i][3]-m)*rs*gg3 + ee3;
        *reinterpret_cast<float4*>(out + (size_t)(n0+lt) * Ec + o0) = v;
    }
}

// ---------------------------------------------------------------------------
extern "C" void kernel_launch(void* const* d_in, const int* in_sizes, int n_in,
                              void* d_out, int out_size)
{
    const float* x     = (const float*)d_in[0];
    const float* Wq    = (const float*)d_in[1];
    const float* bq    = (const float*)d_in[2];
    const float* Wk    = (const float*)d_in[3];
    const float* bk    = (const float*)d_in[4];
    const float* Wv    = (const float*)d_in[5];
    const float* bv    = (const float*)d_in[6];
    const float* Wo    = (const float*)d_in[7];
    const float* bo    = (const float*)d_in[8];
    const float* th_a  = (const float*)d_in[9];
    const float* th_f  = (const float*)d_in[10];
    const float* W1    = (const float*)d_in[11];
    const float* b1    = (const float*)d_in[12];
    const float* W2    = (const float*)d_in[13];
    const float* b2    = (const float*)d_in[14];
    const float* g1    = (const float*)d_in[15];
    const float* be1   = (const float*)d_in[16];
    const float* g2    = (const float*)d_in[17];
    const float* be2   = (const float*)d_in[18];
    float* out = (float*)d_out;

    const size_t SM1 = (8448 + 3*4352 + 192) * sizeof(float);           // 86,784
    const size_t SM2 = (size_t)2 * Tc * DKc * sizeof(float);            // 131,072
    const size_t SM3 = (8448 + 4352 + 192 + 2*2176 + 256) * sizeof(float); // 70,400
    const size_t SM4a = (8448 + 16640 + 256) * sizeof(float);           // 101,376
    const size_t SM4b = (17408 + 192 + 2*2176 + 256) * sizeof(float);   // 88,832

    cudaFuncSetAttribute(qkv_kernel,    cudaFuncAttributeMaxDynamicSharedMemorySize, (int)SM1);
    cudaFuncSetAttribute(attn_kernel,   cudaFuncAttributeMaxDynamicSharedMemorySize, (int)SM2);
    cudaFuncSetAttribute(oproj_kernel,  cudaFuncAttributeMaxDynamicSharedMemorySize, (int)SM3);
    cudaFuncSetAttribute(ffn_h_kernel,  cudaFuncAttributeMaxDynamicSharedMemorySize, (int)SM4a);
    cudaFuncSetAttribute(ffn_out_kernel,cudaFuncAttributeMaxDynamicSharedMemorySize, (int)SM4b);

    qkv_kernel<<<NTOK/128, 256, SM1>>>(x, Wq, bq, Wk, bk, Wv, bv, th_a);
    attn_kernel<<<dim3(Bc*Hc, Tc/512), 512, SM2>>>();
    oproj_kernel<<<NTOK/128, 256, SM3>>>(x, Wo, bo, g1, be1);
    ffn_h_kernel<<<NTOK/128, 256, SM4a>>>(W1, b1, th_f);
    ffn_out_kernel<<<NTOK/128, 256, SM4b>>>(W2, b2, g2, be2, out);
}

// round 6
// speedup vs baseline: 1.9182x; 1.1697x over previous
#include <cuda_runtime.h>
#include <math.h>

#define Bc   8
#define Tc   2048
#define Ec   64
#define Hc   8
#define DKc  8
#define FFc  256
#define NTOK (Bc*Tc)

typedef unsigned long long u64;

// ---- packed f32x2 helpers (bit-exact fp32 per lane) ----
__device__ __forceinline__ u64 pack2(float lo, float hi) {
    u64 r; asm("mov.b64 %0,{%1,%2};" : "=l"(r) : "f"(lo), "f"(hi)); return r;
}
__device__ __forceinline__ u64 dup2(float v) {
    u64 r; asm("mov.b64 %0,{%1,%1};" : "=l"(r) : "f"(v)); return r;
}
__device__ __forceinline__ void unpack2(u64 v, float& a, float& b) {
    asm("mov.b64 {%0,%1},%2;" : "=f"(a), "=f"(b) : "l"(v));
}
__device__ __forceinline__ u64 fma2(u64 a, u64 b, u64 c) {
    u64 d; asm("fma.rn.f32x2 %0,%1,%2,%3;" : "=l"(d) : "l"(a), "l"(b), "l"(c)); return d;
}
__device__ __forceinline__ u64 mul2(u64 a, u64 b) {
    u64 d; asm("mul.rn.f32x2 %0,%1,%2;" : "=l"(d) : "l"(a), "l"(b)); return d;
}
__device__ __forceinline__ u64 add2(u64 a, u64 b) {
    u64 d; asm("add.rn.f32x2 %0,%1,%2;" : "=l"(d) : "l"(a), "l"(b)); return d;
}
__device__ __forceinline__ float ex2f(float s) {
    float p; asm("ex2.approx.f32 %0,%1;" : "=f"(p) : "f"(s)); return p;
}

// Scratch (device globals)
__device__ float g_q[Bc*Hc*Tc*DKc];     // [b,h,t,d]
__device__ float g_k[Bc*Hc*Tc*DKc];
__device__ float g_v[Bc*Hc*Tc*DKc];
__device__ float g_attn[NTOK*Ec];       // [n, e], e = h*8+d
__device__ float g_x1[NTOK*Ec];
__device__ float g_h[(size_t)FFc*NTOK]; // f-major [f, n]

// =====================================================================
// K1: qkv. grid (NTOK/128, 3): blockIdx.y selects matrix (q/k/v).
// Block: 128 tokens x 64 outs, 256 threads, thread tile 8tok x 4out.
// 51KB smem -> 4 CTAs/SM.
// =====================================================================
__global__ __launch_bounds__(256) void qkv_kernel(
    const float* __restrict__ x,
    const float* __restrict__ Wq, const float* __restrict__ bq,
    const float* __restrict__ Wk, const float* __restrict__ bk,
    const float* __restrict__ Wv, const float* __restrict__ bv,
    const float* __restrict__ theta_p)
{
    extern __shared__ float sm[];
    float* xT = sm;                 // [64][132] = 8448
    float* wT = sm + 8448;          // [64][68]  = 4352
    float* sb = wT + 4352;          // 64
    int tid = threadIdx.x;
    int m = blockIdx.y;

    const float* W = (m == 0) ? Wq : (m == 1) ? Wk : Wv;
    const float* bias = (m == 0) ? bq : (m == 1) ? bk : bv;
    float* gout = (m == 0) ? g_q : (m == 1) ? g_k : g_v;

    for (int i = tid; i < 4096; i += 256) {
        int o = i >> 6, k = i & 63;
        wT[k*68+o] = W[i];
    }
    if (tid < 64) sb[tid] = bias[tid];

    int n0 = blockIdx.x * 128;
    const float4* xsrc = reinterpret_cast<const float4*>(x + (size_t)n0 * Ec);
    for (int i = tid; i < 2048; i += 256) {
        int r = i >> 4, eg = i & 15;
        float4 v = xsrc[i];
        xT[(eg*4+0)*132 + r] = v.x;
        xT[(eg*4+1)*132 + r] = v.y;
        xT[(eg*4+2)*132 + r] = v.z;
        xT[(eg*4+3)*132 + r] = v.w;
    }
    __syncthreads();

    float theta = theta_p[0];
    int tokg = tid & 15, outg = tid >> 4;
    int b = n0 >> 11;
    int tt0 = (n0 & 2047) + tokg * 8;
    int o0 = outg * 4, h = o0 >> 3, d0 = o0 & 7;

    u64 acc[4][4];
#pragma unroll
    for (int a = 0; a < 4; a++)
#pragma unroll
        for (int j = 0; j < 4; j++) acc[a][j] = 0;

#pragma unroll 4
    for (int k = 0; k < 64; k++) {
        const ulonglong2* xr = reinterpret_cast<const ulonglong2*>(xT + k*132 + tokg*8);
        ulonglong2 xa = xr[0], xb = xr[1];
        float4 wv = *reinterpret_cast<const float4*>(wT + k*68 + o0);
        u64 w0 = dup2(wv.x), w1 = dup2(wv.y), w2 = dup2(wv.z), w3 = dup2(wv.w);
        acc[0][0]=fma2(xa.x,w0,acc[0][0]); acc[0][1]=fma2(xa.x,w1,acc[0][1]);
        acc[0][2]=fma2(xa.x,w2,acc[0][2]); acc[0][3]=fma2(xa.x,w3,acc[0][3]);
        acc[1][0]=fma2(xa.y,w0,acc[1][0]); acc[1][1]=fma2(xa.y,w1,acc[1][1]);
        acc[1][2]=fma2(xa.y,w2,acc[1][2]); acc[1][3]=fma2(xa.y,w3,acc[1][3]);
        acc[2][0]=fma2(xb.x,w0,acc[2][0]); acc[2][1]=fma2(xb.x,w1,acc[2][1]);
        acc[2][2]=fma2(xb.x,w2,acc[2][2]); acc[2][3]=fma2(xb.x,w3,acc[2][3]);
        acc[3][0]=fma2(xb.y,w0,acc[3][0]); acc[3][1]=fma2(xb.y,w1,acc[3][1]);
        acc[3][2]=fma2(xb.y,w2,acc[3][2]); acc[3][3]=fma2(xb.y,w3,acc[3][3]);
    }
    float bb0 = sb[o0+0]+theta, bb1 = sb[o0+1]+theta,
          bb2 = sb[o0+2]+theta, bb3 = sb[o0+3]+theta;
    size_t gbase = ((size_t)b*Hc + h) * (Tc*DKc) + d0;
#pragma unroll
    for (int tp = 0; tp < 4; tp++) {
        float v00,v10, v01,v11, v02,v12, v03,v13;
        unpack2(acc[tp][0], v00, v10);
        unpack2(acc[tp][1], v01, v11);
        unpack2(acc[tp][2], v02, v12);
        unpack2(acc[tp][3], v03, v13);
        int t0 = tt0 + tp*2;
        float4 r0 = make_float4(__cosf(v00+bb0), __cosf(v01+bb1), __cosf(v02+bb2), __cosf(v03+bb3));
        float4 r1 = make_float4(__cosf(v10+bb0), __cosf(v11+bb1), __cosf(v12+bb2), __cosf(v13+bb3));
        *reinterpret_cast<float4*>(gout + gbase + (size_t)t0*8)     = r0;
        *reinterpret_cast<float4*>(gout + gbase + (size_t)(t0+1)*8) = r1;
    }
}

// =====================================================================
// K2: attention. 512 threads, 2 q-rows per thread (ILP 2), grid (64,2)
// = 128 CTAs = single wave. Paired-key K layout, bounded-score softmax.
// =====================================================================
__global__ __launch_bounds__(512) void attn_kernel()
{
    extern __shared__ float sm[];
    u64* K2p = reinterpret_cast<u64*>(sm);            // [1024][8]  64KB
    u64* V2  = reinterpret_cast<u64*>(sm + 16384);    // [2048][4]  64KB

    int bh  = blockIdx.x;
    int qt  = blockIdx.y;   // 0..1
    int tid = threadIdx.x;

    const float* gk = g_k + (size_t)bh * (Tc*DKc);
#pragma unroll
    for (int i = tid; i < 8192; i += 512) {
        int j2 = i >> 3, d = i & 7;
        K2p[i] = pack2(gk[j2*16 + d], gk[j2*16 + 8 + d]);
    }
    const ulonglong2* gv = reinterpret_cast<const ulonglong2*>(g_v + (size_t)bh * (Tc*DKc));
    ulonglong2* V4 = reinterpret_cast<ulonglong2*>(V2);
#pragma unroll
    for (int i = 0; i < 8; i++) V4[tid + 512*i] = gv[tid + 512*i];
    __syncthreads();

    int t0 = qt * 1024 + tid;
    int t1 = t0 + 512;
    const float QS = 0.35355339059327f * 1.4426950408889634f;  // 1/sqrt(8)*log2(e)
    const float* qp0 = g_q + (size_t)bh * (Tc*DKc) + t0 * DKc;
    const float* qp1 = g_q + (size_t)bh * (Tc*DKc) + t1 * DKc;
    u64 qa[8], qb[8];
#pragma unroll
    for (int d = 0; d < 8; d++) { qa[d] = dup2(qp0[d]*QS); qb[d] = dup2(qp1[d]*QS); }

    u64 la = 0, lb = 0;
    u64 aA0=0, aA1=0, aA2=0, aA3=0;
    u64 aB0=0, aB1=0, aB2=0, aB3=0;

    const ulonglong2* kp = reinterpret_cast<const ulonglong2*>(K2p);
    const ulonglong2* vp = reinterpret_cast<const ulonglong2*>(V2);

#pragma unroll 2
    for (int j2 = 0; j2 < 1024; j2++) {
        ulonglong2 kA = kp[0], kB = kp[1], kC = kp[2], kD = kp[3]; kp += 4;
        u64 sA = mul2(qa[0], kA.x);
        u64 sB = mul2(qb[0], kA.x);
        sA = fma2(qa[1], kA.y, sA);  sB = fma2(qb[1], kA.y, sB);
        sA = fma2(qa[2], kB.x, sA);  sB = fma2(qb[2], kB.x, sB);
        sA = fma2(qa[3], kB.y, sA);  sB = fma2(qb[3], kB.y, sB);
        sA = fma2(qa[4], kC.x, sA);  sB = fma2(qb[4], kC.x, sB);
        sA = fma2(qa[5], kC.y, sA);  sB = fma2(qb[5], kC.y, sB);
        sA = fma2(qa[6], kD.x, sA);  sB = fma2(qb[6], kD.x, sB);
        sA = fma2(qa[7], kD.y, sA);  sB = fma2(qb[7], kD.y, sB);
        float sa0, sa1, sb0, sb1;
        unpack2(sA, sa0, sa1);
        unpack2(sB, sb0, sb1);
        float pa0 = ex2f(sa0), pa1 = ex2f(sa1);
        float pb0 = ex2f(sb0), pb1 = ex2f(sb1);
        ulonglong2 vA = vp[0], vB = vp[1], vC = vp[2], vD = vp[3]; vp += 4;
        u64 ppa0 = dup2(pa0), ppa1 = dup2(pa1);
        u64 ppb0 = dup2(pb0), ppb1 = dup2(pb1);
        la = add2(la, pack2(pa0, pa1));
        lb = add2(lb, pack2(pb0, pb1));
        aA0 = fma2(ppa0, vA.x, aA0); aA1 = fma2(ppa0, vA.y, aA1);
        aA2 = fma2(ppa0, vB.x, aA2); aA3 = fma2(ppa0, vB.y, aA3);
        aA0 = fma2(ppa1, vC.x, aA0); aA1 = fma2(ppa1, vC.y, aA1);
        aA2 = fma2(ppa1, vD.x, aA2); aA3 = fma2(ppa1, vD.y, aA3);
        aB0 = fma2(ppb0, vA.x, aB0); aB1 = fma2(ppb0, vA.y, aB1);
        aB2 = fma2(ppb0, vB.x, aB2); aB3 = fma2(ppb0, vB.y, aB3);
        aB0 = fma2(ppb1, vC.x, aB0); aB1 = fma2(ppb1, vC.y, aB1);
        aB2 = fma2(ppb1, vD.x, aB2); aB3 = fma2(ppb1, vD.y, aB3);
    }

    int b = bh >> 3, h = bh & 7;
    {
        float llo, lhi; unpack2(la, llo, lhi);
        float inv = 1.0f / (llo + lhi);
        float o0,o1,o2,o3,o4,o5,o6,o7;
        unpack2(aA0,o0,o1); unpack2(aA1,o2,o3); unpack2(aA2,o4,o5); unpack2(aA3,o6,o7);
        float* op = g_attn + ((size_t)(b*Tc + t0)) * Ec + h * DKc;
        reinterpret_cast<float4*>(op)[0] = make_float4(o0*inv, o1*inv, o2*inv, o3*inv);
        reinterpret_cast<float4*>(op)[1] = make_float4(o4*inv, o5*inv, o6*inv, o7*inv);
    }
    {
        float llo, lhi; unpack2(lb, llo, lhi);
        float inv = 1.0f / (llo + lhi);
        float o0,o1,o2,o3,o4,o5,o6,o7;
        unpack2(aB0,o0,o1); unpack2(aB1,o2,o3); unpack2(aB2,o4,o5); unpack2(aB3,o6,o7);
        float* op = g_attn + ((size_t)(b*Tc + t1)) * Ec + h * DKc;
        reinterpret_cast<float4*>(op)[0] = make_float4(o0*inv, o1*inv, o2*inv, o3*inv);
        reinterpret_cast<float4*>(op)[1] = make_float4(o4*inv, o5*inv, o6*inv, o7*inv);
    }
}

// =====================================================================
// K3: oproj + LN. GEMM tile 128 tok x 64 out, 256 threads;
// LN via smem partial sums.
// =====================================================================
__global__ __launch_bounds__(256) void oproj_kernel(
    const float* __restrict__ x, const float* __restrict__ Wo,
    const float* __restrict__ bo, const float* __restrict__ g1,
    const float* __restrict__ be1)
{
    extern __shared__ float sm[];
    float* xT   = sm;             // [64][132] = 8448
    float* wT   = sm + 8448;      // [64][68]  = 4352
    float* sbo  = wT + 4352;      // 64
    float* sg   = sbo + 64;       // 64
    float* sbe  = sg + 64;        // 64
    float* red1 = sbe + 64;       // 128*17 = 2176
    float* red2 = red1 + 2176;    // 2176
    float* mS   = red2 + 2176;    // 128
    float* rsS  = mS + 128;       // 128
    int tid = threadIdx.x;

    for (int i = tid; i < 4096; i += 256) {
        int o = i >> 6, k = i & 63;
        wT[k*68+o] = Wo[i];
    }
    if (tid < 64) { sbo[tid] = bo[tid]; sg[tid] = g1[tid]; sbe[tid] = be1[tid]; }

    int n0 = blockIdx.x * 128;
    const float4* asrc = reinterpret_cast<const float4*>(g_attn + (size_t)n0 * Ec);
    for (int i = tid; i < 2048; i += 256) {
        int r = i >> 4, eg = i & 15;
        float4 v = asrc[i];
        xT[(eg*4+0)*132 + r] = v.x;
        xT[(eg*4+1)*132 + r] = v.y;
        xT[(eg*4+2)*132 + r] = v.z;
        xT[(eg*4+3)*132 + r] = v.w;
    }
    __syncthreads();

    int tokg = tid & 15, outg = tid >> 4;
    int o0 = outg * 4;

    u64 acc[4][4];
#pragma unroll
    for (int a = 0; a < 4; a++)
#pragma unroll
        for (int j = 0; j < 4; j++) acc[a][j] = 0;

#pragma unroll 4
    for (int k = 0; k < 64; k++) {
        const ulonglong2* xr = reinterpret_cast<const ulonglong2*>(xT + k*132 + tokg*8);
        ulonglong2 xa = xr[0], xb = xr[1];
        float4 wv = *reinterpret_cast<const float4*>(wT + k*68 + o0);
        u64 w0 = dup2(wv.x), w1 = dup2(wv.y), w2 = dup2(wv.z), w3 = dup2(wv.w);
        acc[0][0]=fma2(xa.x,w0,acc[0][0]); acc[0][1]=fma2(xa.x,w1,acc[0][1]);
        acc[0][2]=fma2(xa.x,w2,acc[0][2]); acc[0][3]=fma2(xa.x,w3,acc[0][3]);
        acc[1][0]=fma2(xa.y,w0,acc[1][0]); acc[1][1]=fma2(xa.y,w1,acc[1][1]);
        acc[1][2]=fma2(xa.y,w2,acc[1][2]); acc[1][3]=fma2(xa.y,w3,acc[1][3]);
        acc[2][0]=fma2(xb.x,w0,acc[2][0]); acc[2][1]=fma2(xb.x,w1,acc[2][1]);
        acc[2][2]=fma2(xb.x,w2,acc[2][2]); acc[2][3]=fma2(xb.x,w3,acc[2][3]);
        acc[3][0]=fma2(xb.y,w0,acc[3][0]); acc[3][1]=fma2(xb.y,w1,acc[3][1]);
        acc[3][2]=fma2(xb.y,w2,acc[3][2]); acc[3][3]=fma2(xb.y,w3,acc[3][3]);
    }

    float bb0 = sbo[o0+0], bb1 = sbo[o0+1], bb2 = sbo[o0+2], bb3 = sbo[o0+3];
    float y[8][4];
#pragma unroll
    for (int tp = 0; tp < 4; tp++) {
        int lt = tokg*8 + tp*2;
        float4 r0 = *reinterpret_cast<const float4*>(x + (size_t)(n0+lt)   * Ec + o0);
        float4 r1 = *reinterpret_cast<const float4*>(x + (size_t)(n0+lt+1) * Ec + o0);
        float v0,v1;
        unpack2(acc[tp][0], v0, v1); y[tp*2][0] = v0 + r0.x + bb0; y[tp*2+1][0] = v1 + r1.x + bb0;
        unpack2(acc[tp][1], v0, v1); y[tp*2][1] = v0 + r0.y + bb1; y[tp*2+1][1] = v1 + r1.y + bb1;
        unpack2(acc[tp][2], v0, v1); y[tp*2][2] = v0 + r0.z + bb2; y[tp*2+1][2] = v1 + r1.z + bb2;
        unpack2(acc[tp][3], v0, v1); y[tp*2][3] = v0 + r0.w + bb3; y[tp*2+1][3] = v1 + r1.w + bb3;
    }
#pragma unroll
    for (int i = 0; i < 8; i++) {
        int lt = tokg*8 + i;
        float s1 = y[i][0]+y[i][1]+y[i][2]+y[i][3];
        float s2 = y[i][0]*y[i][0]+y[i][1]*y[i][1]+y[i][2]*y[i][2]+y[i][3]*y[i][3];
        red1[lt*17 + outg] = s1;
        red2[lt*17 + outg] = s2;
    }
    __syncthreads();
    if (tid < 128) {
        float s1 = 0.f, s2 = 0.f;
#pragma unroll
        for (int o = 0; o < 16; o++) { s1 += red1[tid*17+o]; s2 += red2[tid*17+o]; }
        float m = s1 * (1.f/64.f);
        float var = s2 * (1.f/64.f) - m*m;
        mS[tid] = m;
        rsS[tid] = rsqrtf(var + 1e-5f);
    }
    __syncthreads();

    float gg0 = sg[o0+0], gg1 = sg[o0+1], gg2 = sg[o0+2], gg3 = sg[o0+3];
    float ee0 = sbe[o0+0], ee1 = sbe[o0+1], ee2 = sbe[o0+2], ee3 = sbe[o0+3];
#pragma unroll
    for (int i = 0; i < 8; i++) {
        int lt = tokg*8 + i;
        float m = mS[lt], rs = rsS[lt];
        float4 v;
        v.x = (y[i][0]-m)*rs*gg0 + ee0;
        v.y = (y[i][1]-m)*rs*gg1 + ee1;
        v.z = (y[i][2]-m)*rs*gg2 + ee2;
        v.w = (y[i][3]-m)*rs*gg3 + ee3;
        *reinterpret_cast<float4*>(g_x1 + (size_t)(n0+lt) * Ec + o0) = v;
    }
}

// =====================================================================
// K4a: H[f,n] = relu(cos(x1)*ct @ W1^T + b1). grid (NTOK/128, 2):
// blockIdx.y picks a 128-wide f-half. 17KB smem -> high occupancy.
// =====================================================================
__global__ __launch_bounds__(256) void ffn_h_kernel(
    const float* __restrict__ W1, const float* __restrict__ b1,
    const float* __restrict__ theta_p)
{
    extern __shared__ float sm[];
    float* xT  = sm;             // [64][132] = 8448
    float* w1T = sm + 8448;      // [64][132] = 8448 (128 f's)
    float* sb1 = w1T + 8448;     // 128
    int tid = threadIdx.x;
    int fbase = blockIdx.y * 128;

    for (int i = tid; i < 8192; i += 256) {
        int fl = i >> 6, k = i & 63;
        w1T[k*132 + fl] = W1[(fbase + fl)*64 + k];
    }
    if (tid < 128) sb1[tid] = b1[fbase + tid];

    float ct = __cosf(theta_p[0]);
    int n0 = blockIdx.x * 128;
    const float4* xsrc = reinterpret_cast<const float4*>(g_x1 + (size_t)n0 * Ec);
    for (int i = tid; i < 2048; i += 256) {
        int r = i >> 4, eg = i & 15;
        float4 v = xsrc[i];
        xT[(eg*4+0)*132 + r] = __cosf(v.x)*ct;
        xT[(eg*4+1)*132 + r] = __cosf(v.y)*ct;
        xT[(eg*4+2)*132 + r] = __cosf(v.z)*ct;
        xT[(eg*4+3)*132 + r] = __cosf(v.w)*ct;
    }
    __syncthreads();

    int tokg = tid & 15, outg = tid >> 4;

#pragma unroll
    for (int fpass = 0; fpass < 2; fpass++) {
        int fl0 = fpass*64 + outg*4;
        u64 acc[4][4];
#pragma unroll
        for (int a = 0; a < 4; a++)
#pragma unroll
            for (int j = 0; j < 4; j++) acc[a][j] = 0;

#pragma unroll 4
        for (int k = 0; k < 64; k++) {
            const ulonglong2* xr = reinterpret_cast<const ulonglong2*>(xT + k*132 + tokg*8);
            ulonglong2 xa = xr[0], xb = xr[1];
            float4 wv = *reinterpret_cast<const float4*>(w1T + k*132 + fl0);
            u64 w0 = dup2(wv.x), w1 = dup2(wv.y), w2 = dup2(wv.z), w3 = dup2(wv.w);
            acc[0][0]=fma2(xa.x,w0,acc[0][0]); acc[0][1]=fma2(xa.x,w1,acc[0][1]);
            acc[0][2]=fma2(xa.x,w2,acc[0][2]); acc[0][3]=fma2(xa.x,w3,acc[0][3]);
            acc[1][0]=fma2(xa.y,w0,acc[1][0]); acc[1][1]=fma2(xa.y,w1,acc[1][1]);
            acc[1][2]=fma2(xa.y,w2,acc[1][2]); acc[1][3]=fma2(xa.y,w3,acc[1][3]);
            acc[2][0]=fma2(xb.x,w0,acc[2][0]); acc[2][1]=fma2(xb.x,w1,acc[2][1]);
            acc[2][2]=fma2(xb.x,w2,acc[2][2]); acc[2][3]=fma2(xb.x,w3,acc[2][3]);
            acc[3][0]=fma2(xb.y,w0,acc[3][0]); acc[3][1]=fma2(xb.y,w1,acc[3][1]);
            acc[3][2]=fma2(xb.y,w2,acc[3][2]); acc[3][3]=fma2(xb.y,w3,acc[3][3]);
        }
#pragma unroll
        for (int j = 0; j < 4; j++) {
            int fl = fl0 + j;
            float bb = sb1[fl];
            float v0,v1,v2,v3,v4,v5,v6,v7;
            unpack2(acc[0][j], v0, v1);
            unpack2(acc[1][j], v2, v3);
            unpack2(acc[2][j], v4, v5);
            unpack2(acc[3][j], v6, v7);
            float4 h0 = make_float4(fmaxf(v0+bb,0.f), fmaxf(v1+bb,0.f),
                                    fmaxf(v2+bb,0.f), fmaxf(v3+bb,0.f));
            float4 h1 = make_float4(fmaxf(v4+bb,0.f), fmaxf(v5+bb,0.f),
                                    fmaxf(v6+bb,0.f), fmaxf(v7+bb,0.f));
            float* hp = g_h + (size_t)(fbase + fl) * NTOK + n0 + tokg*8;
            reinterpret_cast<float4*>(hp)[0] = h0;
            reinterpret_cast<float4*>(hp)[1] = h1;
        }
    }
}

// =====================================================================
// K4b: out = LN(x1 + H @ W2^T + b2). K=256, H k-major streamed via LDG.
// =====================================================================
__global__ __launch_bounds__(256) void ffn_out_kernel(
    const float* __restrict__ W2, const float* __restrict__ b2,
    const float* __restrict__ g2, const float* __restrict__ be2,
    float* __restrict__ out)
{
    extern __shared__ float sm[];
    float* w2T  = sm;             // [256][68] = 17408
    float* sb2  = sm + 17408;     // 64
    float* sg   = sb2 + 64;
    float* sbe  = sg + 64;
    float* red1 = sbe + 64;       // 2176
    float* red2 = red1 + 2176;
    float* mS   = red2 + 2176;    // 128
    float* rsS  = mS + 128;
    int tid = threadIdx.x;

    for (int i = tid; i < Ec*FFc; i += 256) {
        int e = i >> 8, f = i & 255;
        w2T[f*68 + e] = W2[i];
    }
    if (tid < 64) { sb2[tid] = b2[tid]; sg[tid] = g2[tid]; sbe[tid] = be2[tid]; }
    __syncthreads();

    int n0 = blockIdx.x * 128;
    int tokg = tid & 15, outg = tid >> 4;
    int o0 = outg * 4;

    u64 acc[4][4];
#pragma unroll
    for (int a = 0; a < 4; a++)
#pragma unroll
        for (int j = 0; j < 4; j++) acc[a][j] = 0;

#pragma unroll 4
    for (int k = 0; k < 256; k++) {
        const ulonglong2* hp = reinterpret_cast<const ulonglong2*>(g_h + (size_t)k * NTOK + n0 + tokg*8);
        ulonglong2 xa = hp[0], xb = hp[1];
        float4 wv = *reinterpret_cast<const float4*>(w2T + k*68 + o0);
        u64 w0 = dup2(wv.x), w1 = dup2(wv.y), w2_ = dup2(wv.z), w3 = dup2(wv.w);
        acc[0][0]=fma2(xa.x,w0,acc[0][0]); acc[0][1]=fma2(xa.x,w1,acc[0][1]);
        acc[0][2]=fma2(xa.x,w2_,acc[0][2]); acc[0][3]=fma2(xa.x,w3,acc[0][3]);
        acc[1][0]=fma2(xa.y,w0,acc[1][0]); acc[1][1]=fma2(xa.y,w1,acc[1][1]);
        acc[1][2]=fma2(xa.y,w2_,acc[1][2]); acc[1][3]=fma2(xa.y,w3,acc[1][3]);
        acc[2][0]=fma2(xb.x,w0,acc[2][0]); acc[2][1]=fma2(xb.x,w1,acc[2][1]);
        acc[2][2]=fma2(xb.x,w2_,acc[2][2]); acc[2][3]=fma2(xb.x,w3,acc[2][3]);
        acc[3][0]=fma2(xb.y,w0,acc[3][0]); acc[3][1]=fma2(xb.y,w1,acc[3][1]);
        acc[3][2]=fma2(xb.y,w2_,acc[3][2]); acc[3][3]=fma2(xb.y,w3,acc[3][3]);
    }

    float bb0 = sb2[o0+0], bb1 = sb2[o0+1], bb2v = sb2[o0+2], bb3 = sb2[o0+3];
    float y[8][4];
#pragma unroll
    for (int tp = 0; tp < 4; tp++) {
        int lt = tokg*8 + tp*2;
        float4 r0 = *reinterpret_cast<const float4*>(g_x1 + (size_t)(n0+lt)   * Ec + o0);
        float4 r1 = *reinterpret_cast<const float4*>(g_x1 + (size_t)(n0+lt+1) * Ec + o0);
        float v0,v1;
        unpack2(acc[tp][0], v0, v1); y[tp*2][0] = v0 + r0.x + bb0; y[tp*2+1][0] = v1 + r1.x + bb0;
        unpack2(acc[tp][1], v0, v1); y[tp*2][1] = v0 + r0.y + bb1; y[tp*2+1][1] = v1 + r1.y + bb1;
        unpack2(acc[tp][2], v0, v1); y[tp*2][2] = v0 + r0.z + bb2v; y[tp*2+1][2] = v1 + r1.z + bb2v;
        unpack2(acc[tp][3], v0, v1); y[tp*2][3] = v0 + r0.w + bb3; y[tp*2+1][3] = v1 + r1.w + bb3;
    }
#pragma unroll
    for (int i = 0; i < 8; i++) {
        int lt = tokg*8 + i;
        float s1 = y[i][0]+y[i][1]+y[i][2]+y[i][3];
        float s2 = y[i][0]*y[i][0]+y[i][1]*y[i][1]+y[i][2]*y[i][2]+y[i][3]*y[i][3];
        red1[lt*17 + outg] = s1;
        red2[lt*17 + outg] = s2;
    }
    __syncthreads();
    if (tid < 128) {
        float s1 = 0.f, s2 = 0.f;
#pragma unroll
        for (int o = 0; o < 16; o++) { s1 += red1[tid*17+o]; s2 += red2[tid*17+o]; }
        float m = s1 * (1.f/64.f);
        float var = s2 * (1.f/64.f) - m*m;
        mS[tid] = m;
        rsS[tid] = rsqrtf(var + 1e-5f);
    }
    __syncthreads();

    float gg0 = sg[o0+0], gg1 = sg[o0+1], gg2 = sg[o0+2], gg3 = sg[o0+3];
    float ee0 = sbe[o0+0], ee1 = sbe[o0+1], ee2 = sbe[o0+2], ee3 = sbe[o0+3];
#pragma unroll
    for (int i = 0; i < 8; i++) {
        int lt = tokg*8 + i;
        float m = mS[lt], rs = rsS[lt];
        float4 v;
        v.x = (y[i][0]-m)*rs*gg0 + ee0;
        v.y = (y[i][1]-m)*rs*gg1 + ee1;
        v.z = (y[i][2]-m)*rs*gg2 + ee2;
        v.w = (y[i][3]-m)*rs*gg3 + ee3;
        *reinterpret_cast<float4*>(out + (size_t)(n0+lt) * Ec + o0) = v;
    }
}

// ---------------------------------------------------------------------------
extern "C" void kernel_launch(void* const* d_in, const int* in_sizes, int n_in,
                              void* d_out, int out_size)
{
    const float* x     = (const float*)d_in[0];
    const float* Wq    = (const float*)d_in[1];
    const float* bq    = (const float*)d_in[2];
    const float* Wk    = (const float*)d_in[3];
    const float* bk    = (const float*)d_in[4];
    const float* Wv    = (const float*)d_in[5];
    const float* bv    = (const float*)d_in[6];
    const float* Wo    = (const float*)d_in[7];
    const float* bo    = (const float*)d_in[8];
    const float* th_a  = (const float*)d_in[9];
    const float* th_f  = (const float*)d_in[10];
    const float* W1    = (const float*)d_in[11];
    const float* b1    = (const float*)d_in[12];
    const float* W2    = (const float*)d_in[13];
    const float* b2    = (const float*)d_in[14];
    const float* g1    = (const float*)d_in[15];
    const float* be1   = (const float*)d_in[16];
    const float* g2    = (const float*)d_in[17];
    const float* be2   = (const float*)d_in[18];
    float* out = (float*)d_out;

    const size_t SM1 = (8448 + 4352 + 64) * sizeof(float);                 // 51,456
    const size_t SM2 = (size_t)2 * Tc * DKc * sizeof(float);               // 131,072
    const size_t SM3 = (8448 + 4352 + 192 + 2*2176 + 256) * sizeof(float); // 70,400
    const size_t SM4a = (8448 + 8448 + 128) * sizeof(float);               // 68,096
    const size_t SM4b = (17408 + 192 + 2*2176 + 256) * sizeof(float);      // 88,832

    cudaFuncSetAttribute(qkv_kernel,    cudaFuncAttributeMaxDynamicSharedMemorySize, (int)SM1);
    cudaFuncSetAttribute(attn_kernel,   cudaFuncAttributeMaxDynamicSharedMemorySize, (int)SM2);
    cudaFuncSetAttribute(oproj_kernel,  cudaFuncAttributeMaxDynamicSharedMemorySize, (int)SM3);
    cudaFuncSetAttribute(ffn_h_kernel,  cudaFuncAttributeMaxDynamicSharedMemorySize, (int)SM4a);
    cudaFuncSetAttribute(ffn_out_kernel,cudaFuncAttributeMaxDynamicSharedMemorySize, (int)SM4b);

    qkv_kernel<<<dim3(NTOK/128, 3), 256, SM1>>>(x, Wq, bq, Wk, bk, Wv, bv, th_a);
    attn_kernel<<<dim3(Bc*Hc, 2), 512, SM2>>>();
    oproj_kernel<<<NTOK/128, 256, SM3>>>(x, Wo, bo, g1, be1);
    ffn_h_kernel<<<dim3(NTOK/128, 2), 256, SM4a>>>(W1, b1, th_f);
    ffn_out_kernel<<<NTOK/128, 256, SM4b>>>(W2, b2, g2, be2, out);
}